// round 4
// baseline (speedup 1.0000x reference)
#include <cuda_runtime.h>
#include <cuda_bf16.h>
#include <math.h>
#include <stdint.h>

// ============================================================
// Static device scratch
// ============================================================
__device__ float g_x[512 * 1024];        // attention state, C-major (c, tok)
__device__ float g_t[1024 * 512];        // V token-major (tok, vfeat)
__device__ float g_qkv[1536 * 1024];     // Q,K feature-major (feat, tok)
__device__ float g_attn[8 * 1024 * 1024];
__device__ float g_res[512 * 1024];      // attn out feature-major (feat, tok)
__device__ float g_xs[512 * 2500];
__device__ float g_h[512 * 2500];
__device__ float g_r[512 * 2500];
__device__ float g_tmp[512 * 2500];
__device__ float g_u[512 * 10000];
__device__ float g_y1[512 * 10000];
__device__ float g_y2[512 * 10000];
__device__ float g_bn[2048];

// conv weights presplit (hi+lo)
#define W_HEAD  0
#define W_BODY  2359296
#define W_BTAIL 40108032
#define W_UP    42467328
#define W_TAIL  51904512
#define W_C1    54263808
#define W_C2    56623104
#define W_TOTAL 58982400
__device__ __nv_bfloat16 g_whi[W_TOTAL];
__device__ __nv_bfloat16 g_wlo[W_TOTAL];
// attention weights presplit + transposed: qkv (8,1536,512), proj (8,512,512)
__device__ __nv_bfloat16 g_aqh[8 * 1536 * 512];
__device__ __nv_bfloat16 g_aql[8 * 1536 * 512];
__device__ __nv_bfloat16 g_aph[8 * 512 * 512];
__device__ __nv_bfloat16 g_apl[8 * 512 * 512];

// ============================================================
// Helpers
// ============================================================
__device__ __forceinline__ uint32_t smem_u32(const void* p) {
    uint32_t a;
    asm("{ .reg .u64 t; cvta.to.shared.u64 t, %1; cvt.u32.u64 %0, t; }"
        : "=r"(a) : "l"(p));
    return a;
}

__device__ __forceinline__ void cpasync16(uint32_t dst, const void* src) {
    asm volatile("cp.async.ca.shared.global [%0], [%1], 16;" :: "r"(dst), "l"(src));
}
#define CP_COMMIT asm volatile("cp.async.commit_group;" ::: "memory")
#define CP_WAIT0  asm volatile("cp.async.wait_group 0;" ::: "memory")

__device__ __forceinline__ void ldsm4(uint32_t addr, uint32_t* r) {
    asm volatile("ldmatrix.sync.aligned.m8n8.x4.shared.b16 {%0,%1,%2,%3}, [%4];"
                 : "=r"(r[0]), "=r"(r[1]), "=r"(r[2]), "=r"(r[3]) : "r"(addr));
}

__device__ __forceinline__ void mma16816(float* d, const uint32_t* a,
                                         uint32_t b0, uint32_t b1) {
    asm volatile(
        "mma.sync.aligned.m16n8k16.row.col.f32.bf16.bf16.f32 "
        "{%0,%1,%2,%3}, {%4,%5,%6,%7}, {%8,%9}, {%0,%1,%2,%3};"
        : "+f"(d[0]), "+f"(d[1]), "+f"(d[2]), "+f"(d[3])
        : "r"(a[0]), "r"(a[1]), "r"(a[2]), "r"(a[3]), "r"(b0), "r"(b1));
}

__device__ __forceinline__ void split2(float v0, float v1, uint32_t& hp, uint32_t& lp) {
    __nv_bfloat16 h0 = __float2bfloat16(v0), h1 = __float2bfloat16(v1);
    __nv_bfloat16 l0 = __float2bfloat16(v0 - __bfloat162float(h0));
    __nv_bfloat16 l1 = __float2bfloat16(v1 - __bfloat162float(h1));
    hp = (uint32_t)__bfloat16_as_ushort(h0) | ((uint32_t)__bfloat16_as_ushort(h1) << 16);
    lp = (uint32_t)__bfloat16_as_ushort(l0) | ((uint32_t)__bfloat16_as_ushort(l1) << 16);
}

// ============================================================
// Weight prep kernels
// ============================================================
__global__ void k_wprep(const float* __restrict__ src, __nv_bfloat16* __restrict__ hi,
                        __nv_bfloat16* __restrict__ lo, int n) {
    int i = blockIdx.x * 256 + threadIdx.x;
    if (i >= n) return;
    float v = src[i];
    __nv_bfloat16 h = __float2bfloat16(v);
    hi[i] = h;
    lo[i] = __float2bfloat16(v - __bfloat162float(h));
}

// qkv_w (8,512,1536) -> transposed (8,1536,512)
__global__ void k_wtq(const float* __restrict__ src, __nv_bfloat16* __restrict__ hi,
                      __nv_bfloat16* __restrict__ lo) {
    int idx = blockIdx.x * 256 + threadIdx.x;
    if (idx >= 8 * 1536 * 512) return;
    int blk = idx / (1536 * 512), r = idx - blk * (1536 * 512);
    int f = r >> 9, c = r & 511;
    float v = src[(size_t)blk * 512 * 1536 + c * 1536 + f];
    __nv_bfloat16 h = __float2bfloat16(v);
    hi[idx] = h;
    lo[idx] = __float2bfloat16(v - __bfloat162float(h));
}

// proj_w (8,512,512) -> transposed (8,512,512)
__global__ void k_wtp(const float* __restrict__ src, __nv_bfloat16* __restrict__ hi,
                      __nv_bfloat16* __restrict__ lo) {
    int idx = blockIdx.x * 256 + threadIdx.x;
    if (idx >= 8 * 512 * 512) return;
    int blk = idx / (512 * 512), r = idx - blk * (512 * 512);
    int f = r >> 9, c = r & 511;
    float v = src[(size_t)blk * 512 * 512 + c * 512 + f];
    __nv_bfloat16 h = __float2bfloat16(v);
    hi[idx] = h;
    lo[idx] = __float2bfloat16(v - __bfloat162float(h));
}

// ============================================================
// Generic tensor GEMM: C[M,N] = A[M,K] @ B[K,N], 3-term bf16 split.
// CTA tile M=128 x N=64, K chunks of 32, double-buffered.
// AM: 0 = presplit bf16 [m][k] (cp.async); 1 = fp32 [k][m]; 2 = fp32 [m][k]
// BM: 0 = fp32 [k][n] direct; 1 = fp32 im2col 3x3 over planes [ci][H*W]
// ============================================================
#define PITCH 80
#define OFF_ALO (128 * PITCH)
#define OFF_BHI (2 * 128 * PITCH)
#define OFF_BLO (OFF_BHI + 64 * PITCH)
#define STAGE   (OFF_BLO + 64 * PITCH)   // 30720
#define SMEM_DYN (2 * STAGE)             // 61440

struct GP {
    const __nv_bfloat16* Ahi;
    const __nv_bfloat16* Alo;
    const float* Af;
    const float* Bf;
    float* out;
    const float* bias;
    const float* bnsc;
    const float* bnsh;
    const float* resid;
    long aoz, boz, coz;
    int K, lda, ldb, ldo, Nn, H, W, relu, ps, trans;
    float scale;
};

template <int AM, int BM>
__global__ __launch_bounds__(256, 2)
void k_tgemm(GP g) {
    extern __shared__ char sm[];
    int tid = threadIdx.x, wid = tid >> 5, lane = tid & 31;
    int n0 = blockIdx.x * 64, m0 = blockIdx.y * 128, z = blockIdx.z;
    uint32_t sb = smem_u32(sm);
    int NCH = g.K >> 5;

    const float* Bf = g.Bf + (size_t)z * g.boz;
    float* outp = g.out + (size_t)z * g.coz;

    // ---- A loader state ----
    int arow = tid >> 1, aseg = tid & 1;
    int krow = tid >> 3, mseg = tid & 7;
    const __nv_bfloat16 *whp = nullptr, *wlp = nullptr;
    const float* afp = nullptr;
    if constexpr (AM == 0) {
        whp = g.Ahi + (size_t)z * g.aoz + (size_t)(m0 + arow) * g.lda + aseg * 16;
        wlp = g.Alo + (size_t)z * g.aoz + (size_t)(m0 + arow) * g.lda + aseg * 16;
    } else if constexpr (AM == 1) {
        afp = g.Af + (size_t)z * g.aoz + (size_t)krow * g.lda + m0 + mseg * 16;
    } else {
        afp = g.Af + (size_t)z * g.aoz + (size_t)(m0 + arow) * g.lda + aseg * 16;
    }
    uint32_t a_off = arow * PITCH + aseg * 32;   // byte offset in A region

    // ---- B loader state ----
    int bpix = tid & 63, bkg = tid >> 6;
    int pg = n0 + bpix;
    bool pval = pg < g.Nn;
    int pc = pval ? pg : 0;
    int py = pc / g.W, px = pc - py * g.W;
    uint32_t b_off = OFF_BHI + bpix * PITCH + bkg * 16;

    float rA[16];
    float rB[8];

    auto a_issue = [&](int ch, int buf) {
        int kk = ch << 5;
        uint32_t bo = buf * STAGE;
        if constexpr (AM == 0) {
            uint32_t d0 = sb + a_off + bo;
            cpasync16(d0, whp + kk);
            cpasync16(d0 + 16, whp + kk + 8);
            cpasync16(d0 + OFF_ALO, wlp + kk);
            cpasync16(d0 + OFF_ALO + 16, wlp + kk + 8);
        } else if constexpr (AM == 1) {
            const float* p = afp + (size_t)kk * g.lda;
            *(float4*)(rA + 0) = *(const float4*)(p + 0);
            *(float4*)(rA + 4) = *(const float4*)(p + 4);
            *(float4*)(rA + 8) = *(const float4*)(p + 8);
            *(float4*)(rA + 12) = *(const float4*)(p + 12);
        } else if constexpr (AM == 2) {
            const float* p = afp + kk;
            *(float4*)(rA + 0) = *(const float4*)(p + 0);
            *(float4*)(rA + 4) = *(const float4*)(p + 4);
            *(float4*)(rA + 8) = *(const float4*)(p + 8);
            *(float4*)(rA + 12) = *(const float4*)(p + 12);
        }
    };

    auto a_store = [&](int buf) {
        uint32_t bo = buf * STAGE;
        if constexpr (AM == 1) {
#pragma unroll
            for (int j = 0; j < 16; j++) {
                float v = rA[j];
                __nv_bfloat16 h = __float2bfloat16(v);
                __nv_bfloat16 l = __float2bfloat16(v - __bfloat162float(h));
                uint32_t off = (mseg * 16 + j) * PITCH + krow * 2;
                *(__nv_bfloat16*)(sm + bo + off) = h;
                *(__nv_bfloat16*)(sm + bo + OFF_ALO + off) = l;
            }
        } else if constexpr (AM == 2) {
            uint32_t hp[8], lp[8];
#pragma unroll
            for (int j = 0; j < 8; j++) split2(rA[2 * j], rA[2 * j + 1], hp[j], lp[j]);
            *(uint4*)(sm + bo + a_off) = *(uint4*)hp;
            *(uint4*)(sm + bo + a_off + 16) = *(uint4*)(hp + 4);
            *(uint4*)(sm + bo + OFF_ALO + a_off) = *(uint4*)lp;
            *(uint4*)(sm + bo + OFF_ALO + a_off + 16) = *(uint4*)(lp + 4);
        }
    };

    auto b_load = [&](int ch) {
        int kk = ch << 5;
#pragma unroll
        for (int j = 0; j < 8; j++) {
            int k = kk + bkg * 8 + j;
            float v = 0.f;
            if constexpr (BM == 1) {
                int ci = k / 9;
                int r9 = k - ci * 9;
                int ky = r9 / 3;
                int dy = ky - 1, dx = (r9 - ky * 3) - 1;
                int yy = py + dy, xx = px + dx;
                if (pval && (unsigned)yy < (unsigned)g.H && (unsigned)xx < (unsigned)g.W)
                    v = Bf[(size_t)ci * g.Nn + yy * g.W + xx];
            } else {
                v = Bf[(size_t)k * g.ldb + n0 + bpix];
            }
            rB[j] = v;
        }
    };

    auto b_store = [&](int buf) {
        uint32_t bo = buf * STAGE;
#pragma unroll
        for (int j = 0; j < 8; j += 2) {
            uint32_t hp, lp;
            split2(rB[j], rB[j + 1], hp, lp);
            *(uint32_t*)(sm + b_off + bo + j * 2) = hp;
            *(uint32_t*)(sm + b_off + bo + (OFF_BLO - OFF_BHI) + j * 2) = lp;
        }
    };

    // ---- MMA assignments ----
    int warp_m = wid & 3, warp_n = wid >> 2;
    uint32_t a_ld = sb + (warp_m * 32 + (lane & 15)) * PITCH + (lane >> 4) * 16;
    uint32_t b_ld = sb + OFF_BHI + (warp_n * 32 + (lane & 15)) * PITCH + (lane >> 4) * 16;

    float acc[2][4][4];
#pragma unroll
    for (int i = 0; i < 2; i++)
#pragma unroll
        for (int j = 0; j < 4; j++)
#pragma unroll
            for (int e = 0; e < 4; e++) acc[i][j][e] = 0.f;

    // prologue
    a_issue(0, 0);
    b_load(0);
    a_store(0);
    b_store(0);
    if constexpr (AM == 0) { CP_COMMIT; CP_WAIT0; }
    __syncthreads();

    for (int ch = 0; ch < NCH; ch++) {
        if (ch + 1 < NCH) {
            a_issue(ch + 1, (ch + 1) & 1);
            b_load(ch + 1);
        }
        uint32_t bo = (ch & 1) * STAGE;
#pragma unroll
        for (int ks = 0; ks < 2; ks++) {
            uint32_t Ah[2][4], Al[2][4], Bh[2][4], Bl[2][4];
#pragma unroll
            for (int mt = 0; mt < 2; mt++) {
                ldsm4(a_ld + bo + mt * (16 * PITCH) + ks * 32, Ah[mt]);
                ldsm4(a_ld + bo + OFF_ALO + mt * (16 * PITCH) + ks * 32, Al[mt]);
            }
#pragma unroll
            for (int gq = 0; gq < 2; gq++) {
                ldsm4(b_ld + bo + gq * (16 * PITCH) + ks * 32, Bh[gq]);
                ldsm4(b_ld + bo + (OFF_BLO - OFF_BHI) + gq * (16 * PITCH) + ks * 32, Bl[gq]);
            }
#pragma unroll
            for (int mt = 0; mt < 2; mt++)
#pragma unroll
                for (int nt = 0; nt < 4; nt++) {
                    int gq = nt >> 1, idx = nt & 1;
                    uint32_t bh0 = Bh[gq][idx], bh1 = Bh[gq][idx + 2];
                    uint32_t bl0 = Bl[gq][idx], bl1 = Bl[gq][idx + 2];
                    mma16816(acc[mt][nt], Ah[mt], bh0, bh1);
                    mma16816(acc[mt][nt], Ah[mt], bl0, bl1);
                    mma16816(acc[mt][nt], Al[mt], bh0, bh1);
                }
        }
        if (ch + 1 < NCH) {
            a_store((ch + 1) & 1);
            b_store((ch + 1) & 1);
            if constexpr (AM == 0) { CP_COMMIT; CP_WAIT0; }
            __syncthreads();
        }
    }

    // ---- epilogue ----
#pragma unroll
    for (int mt = 0; mt < 2; mt++) {
#pragma unroll
        for (int half = 0; half < 2; half++) {
            int co = m0 + warp_m * 32 + mt * 16 + (lane >> 2) + half * 8;
            float bv = g.bias ? g.bias[co] : 0.f;
            float sc = g.bnsc ? g.bnsc[co] : 1.f;
            float sh = g.bnsh ? g.bnsh[co] : 0.f;
#pragma unroll
            for (int nt = 0; nt < 4; nt++) {
#pragma unroll
                for (int e = 0; e < 2; e++) {
                    int p = n0 + warp_n * 32 + nt * 8 + (lane & 3) * 2 + e;
                    if (p >= g.Nn) continue;
                    float v = acc[mt][nt][half * 2 + e] * g.scale;
                    v += bv;
                    if (g.bnsc) v = v * sc + sh;
                    if (g.resid) v += g.resid[(size_t)co * g.ldo + p];
                    if (g.relu) v = fmaxf(v, 0.f);
                    if (g.ps) {
                        int c = co >> 2, ry = (co >> 1) & 1, rx = co & 1;
                        int yy = p / g.W, xx = p - (p / g.W) * g.W;
                        outp[(size_t)c * (4 * g.Nn) + (size_t)(2 * yy + ry) * (2 * g.W) +
                             2 * xx + rx] = v;
                    } else if (g.trans) {
                        outp[(size_t)p * g.ldo + co] = v;
                    } else {
                        outp[(size_t)co * g.ldo + p] = v;
                    }
                }
            }
        }
    }
}

// ============================================================
// Softmax (scale pre-applied by scores epilogue)
// ============================================================
__global__ __launch_bounds__(256)
void k_softmax() {
    float* p = g_attn + (size_t)blockIdx.x * 1024;
    int tid = threadIdx.x;
    float4 v = *(float4*)(p + tid * 4);
    float mx = fmaxf(fmaxf(v.x, v.y), fmaxf(v.z, v.w));
#pragma unroll
    for (int o = 16; o > 0; o >>= 1) mx = fmaxf(mx, __shfl_xor_sync(0xffffffffu, mx, o));
    __shared__ float smx[8], ssm[8];
    if ((tid & 31) == 0) smx[tid >> 5] = mx;
    __syncthreads();
    mx = smx[0];
#pragma unroll
    for (int i = 1; i < 8; i++) mx = fmaxf(mx, smx[i]);
    float e0 = expf(v.x - mx), e1 = expf(v.y - mx), e2 = expf(v.z - mx), e3 = expf(v.w - mx);
    float s = e0 + e1 + e2 + e3;
#pragma unroll
    for (int o = 16; o > 0; o >>= 1) s += __shfl_xor_sync(0xffffffffu, s, o);
    if ((tid & 31) == 0) ssm[tid >> 5] = s;
    __syncthreads();
    s = ssm[0] + ssm[1] + ssm[2] + ssm[3] + ssm[4] + ssm[5] + ssm[6] + ssm[7];
    float inv = 1.f / s;
    *(float4*)(p + tid * 4) = make_float4(e0 * inv, e1 * inv, e2 * inv, e3 * inv);
}

// ============================================================
// Grid sample, BN fold, c3
// ============================================================
__device__ __forceinline__ int map_idx(int o, int size, bool* valid) {
    float vv = -49.f + 2.f * (float)o;
    float gg = (vv + 51.2f) / 102.4f * 2.f - 1.f;
    float f = ((gg + 1.f) * (float)size - 1.f) * 0.5f;
    int ii = (int)rintf(f);
    *valid = (ii >= 0) && (ii < size);
    return min(max(ii, 0), size - 1);
}

__global__ void k_gridsample() {
    int idx = blockIdx.x * 256 + threadIdx.x;
    if (idx >= 512 * 2500) return;
    int c = idx / 2500, p = idx - c * 2500;
    int oy = p / 50, ox = p - oy * 50;
    bool vy, vx;
    int iy = map_idx(oy, 32, &vy);
    int ix = map_idx(ox, 32, &vx);
    g_xs[idx] = (vy && vx) ? g_x[(size_t)c * 1024 + iy * 32 + ix] : 0.f;
}

__global__ void k_bnprep(const float* g1, const float* b1, const float* m1, const float* v1,
                         const float* g2, const float* b2, const float* m2, const float* v2) {
    int c = blockIdx.x * 256 + threadIdx.x;
    if (c >= 512) return;
    float s1 = g1[c] / sqrtf(v1[c] + 1e-5f);
    g_bn[c] = s1;
    g_bn[512 + c] = b1[c] - m1[c] * s1;
    float s2 = g2[c] / sqrtf(v2[c] + 1e-5f);
    g_bn[1024 + c] = s2;
    g_bn[1536 + c] = b2[c] - m2[c] * s2;
}

__global__ void k_c3(const float* __restrict__ w, const float* __restrict__ b,
                     float* __restrict__ out) {
    int idx = blockIdx.x * 256 + threadIdx.x;
    if (idx >= 60000) return;
    int cls = idx / 10000, p = idx - cls * 10000;
    const float* wr = w + cls * 512;
    float s = b[cls];
#pragma unroll 4
    for (int c = 0; c < 512; c++) s += g_y1[(size_t)c * 10000 + p] * wr[c];
    out[idx] = 1.f / (1.f + expf(-s));
}

// ============================================================
// Host orchestration
// ============================================================
static GP gp_base() {
    GP g;
    g.Ahi = nullptr; g.Alo = nullptr; g.Af = nullptr; g.Bf = nullptr;
    g.out = nullptr; g.bias = nullptr; g.bnsc = nullptr; g.bnsh = nullptr;
    g.resid = nullptr;
    g.aoz = 0; g.boz = 0; g.coz = 0;
    g.K = 0; g.lda = 0; g.ldb = 0; g.ldo = 0; g.Nn = 0; g.H = 1; g.W = 1;
    g.relu = 0; g.ps = 0; g.trans = 0; g.scale = 1.f;
    return g;
}

extern "C" void kernel_launch(void* const* d_in, const int* in_sizes, int n_in,
                              void* d_out, int out_size) {
    const float* x       = (const float*)d_in[0];
    const float* qkv_w   = (const float*)d_in[1];
    const float* proj_w  = (const float*)d_in[2];
    const float* proj_b  = (const float*)d_in[3];
    const float* head_w  = (const float*)d_in[4];
    const float* head_b  = (const float*)d_in[5];
    const float* body_w  = (const float*)d_in[6];
    const float* body_b  = (const float*)d_in[7];
    const float* btail_w = (const float*)d_in[8];
    const float* btail_b = (const float*)d_in[9];
    const float* up_w    = (const float*)d_in[10];
    const float* up_b    = (const float*)d_in[11];
    const float* tail_w  = (const float*)d_in[12];
    const float* tail_b  = (const float*)d_in[13];
    const float* c1_w    = (const float*)d_in[14];
    const float* bn1_g   = (const float*)d_in[15];
    const float* bn1_b   = (const float*)d_in[16];
    const float* bn1_m   = (const float*)d_in[17];
    const float* bn1_v   = (const float*)d_in[18];
    const float* c2_w    = (const float*)d_in[19];
    const float* bn2_g   = (const float*)d_in[20];
    const float* bn2_b   = (const float*)d_in[21];
    const float* bn2_m   = (const float*)d_in[22];
    const float* bn2_v   = (const float*)d_in[23];
    const float* c3_w    = (const float*)d_in[24];
    const float* c3_b    = (const float*)d_in[25];
    float* out = (float*)d_out;

    float *p_x, *p_t, *p_qkv, *p_attn, *p_res, *p_xs, *p_h, *p_r, *p_tmp, *p_u, *p_y1, *p_y2, *p_bn;
    __nv_bfloat16 *p_whi, *p_wlo, *p_aqh, *p_aql, *p_aph, *p_apl;
    cudaGetSymbolAddress((void**)&p_x, g_x);
    cudaGetSymbolAddress((void**)&p_t, g_t);
    cudaGetSymbolAddress((void**)&p_qkv, g_qkv);
    cudaGetSymbolAddress((void**)&p_attn, g_attn);
    cudaGetSymbolAddress((void**)&p_res, g_res);
    cudaGetSymbolAddress((void**)&p_xs, g_xs);
    cudaGetSymbolAddress((void**)&p_h, g_h);
    cudaGetSymbolAddress((void**)&p_r, g_r);
    cudaGetSymbolAddress((void**)&p_tmp, g_tmp);
    cudaGetSymbolAddress((void**)&p_u, g_u);
    cudaGetSymbolAddress((void**)&p_y1, g_y1);
    cudaGetSymbolAddress((void**)&p_y2, g_y2);
    cudaGetSymbolAddress((void**)&p_bn, g_bn);
    cudaGetSymbolAddress((void**)&p_whi, g_whi);
    cudaGetSymbolAddress((void**)&p_wlo, g_wlo);
    cudaGetSymbolAddress((void**)&p_aqh, g_aqh);
    cudaGetSymbolAddress((void**)&p_aql, g_aql);
    cudaGetSymbolAddress((void**)&p_aph, g_aph);
    cudaGetSymbolAddress((void**)&p_apl, g_apl);

    cudaFuncSetAttribute(k_tgemm<0, 1>, cudaFuncAttributeMaxDynamicSharedMemorySize, SMEM_DYN);
    cudaFuncSetAttribute(k_tgemm<0, 0>, cudaFuncAttributeMaxDynamicSharedMemorySize, SMEM_DYN);
    cudaFuncSetAttribute(k_tgemm<1, 0>, cudaFuncAttributeMaxDynamicSharedMemorySize, SMEM_DYN);
    cudaFuncSetAttribute(k_tgemm<2, 0>, cudaFuncAttributeMaxDynamicSharedMemorySize, SMEM_DYN);

    cudaMemcpyAsync(p_x, x, (size_t)512 * 1024 * sizeof(float),
                    cudaMemcpyDeviceToDevice, 0);

    // ---- weight prep ----
    {
        struct { const float* s; int off; int n; } regs[7] = {
            {head_w,  W_HEAD,  2359296},
            {body_w,  W_BODY,  37748736},
            {btail_w, W_BTAIL, 2359296},
            {up_w,    W_UP,    9437184},
            {tail_w,  W_TAIL,  2359296},
            {c1_w,    W_C1,    2359296},
            {c2_w,    W_C2,    2359296},
        };
        for (int i = 0; i < 7; i++)
            k_wprep<<<(regs[i].n + 255) / 256, 256>>>(regs[i].s, p_whi + regs[i].off,
                                                      p_wlo + regs[i].off, regs[i].n);
        k_wtq<<<(8 * 1536 * 512 + 255) / 256, 256>>>(qkv_w, p_aqh, p_aql);
        k_wtp<<<(8 * 512 * 512 + 255) / 256, 256>>>(proj_w, p_aph, p_apl);
    }

    const float scale = 0.044194173824159216f;  // 512^-0.5

    // ---- 8 self-attention blocks (tensor cores) ----
    for (int i = 0; i < 8; i++) {
        // QK: M=1024 feat x N=1024 tok, K=512
        {
            GP g = gp_base();
            g.Ahi = p_aqh + (size_t)i * 1536 * 512;
            g.Alo = p_aql + (size_t)i * 1536 * 512;
            g.Bf = p_x; g.out = p_qkv;
            g.K = 512; g.lda = 512; g.ldb = 1024; g.ldo = 1024; g.Nn = 1024;
            k_tgemm<0, 0><<<dim3(16, 8, 1), 256, SMEM_DYN>>>(g);
        }
        // V: M=512 x N=1024, trans-store token-major into g_t
        {
            GP g = gp_base();
            g.Ahi = p_aqh + (size_t)i * 1536 * 512 + 1024 * 512;
            g.Alo = p_aql + (size_t)i * 1536 * 512 + 1024 * 512;
            g.Bf = p_x; g.out = p_t;
            g.K = 512; g.lda = 512; g.ldb = 1024; g.ldo = 512; g.Nn = 1024;
            g.trans = 1;
            k_tgemm<0, 0><<<dim3(16, 4, 1), 256, SMEM_DYN>>>(g);
        }
        // scores: per head S = Q^T K * scale
        {
            GP g = gp_base();
            g.Af = p_qkv; g.aoz = 64 * 1024;
            g.Bf = p_qkv + 512 * 1024; g.boz = 64 * 1024;
            g.out = p_attn; g.coz = 1l << 20;
            g.K = 64; g.lda = 1024; g.ldb = 1024; g.ldo = 1024; g.Nn = 1024;
            g.scale = scale;
            k_tgemm<1, 0><<<dim3(16, 8, 8), 256, SMEM_DYN>>>(g);
        }
        k_softmax<<<8192, 256>>>();
        // AV: per head O = P V, trans-store feature-major into g_res
        {
            GP g = gp_base();
            g.Af = p_attn; g.aoz = 1l << 20;
            g.Bf = p_t; g.boz = 64;
            g.out = p_res; g.coz = 64 * 1024;
            g.K = 1024; g.lda = 1024; g.ldb = 512; g.ldo = 1024; g.Nn = 64;
            g.trans = 1;
            k_tgemm<2, 0><<<dim3(1, 8, 8), 256, SMEM_DYN>>>(g);
        }
        // proj: M=512 x N=1024, accumulate into g_x
        {
            GP g = gp_base();
            g.Ahi = p_aph + (size_t)i * 512 * 512;
            g.Alo = p_apl + (size_t)i * 512 * 512;
            g.Bf = p_res; g.out = p_x; g.resid = p_x;
            g.bias = proj_b + (size_t)i * 512;
            g.K = 512; g.lda = 512; g.ldb = 1024; g.ldo = 1024; g.Nn = 1024;
            k_tgemm<0, 0><<<dim3(16, 4, 1), 256, SMEM_DYN>>>(g);
        }
    }

    // ---- grid transform + BN fold ----
    k_gridsample<<<(512 * 2500 + 255) / 256, 256>>>();
    k_bnprep<<<2, 256>>>(bn1_g, bn1_b, bn1_m, bn1_v, bn2_g, bn2_b, bn2_m, bn2_v);

    // ---- EDSR upsampler ----
    auto conv = [&](const float* in, int woff, const float* bias, const float* bnsc,
                    const float* bnsh, const float* resid, float* o, int H, int W,
                    int relu, int ps, int mblk) {
        GP g = gp_base();
        g.Ahi = p_whi + woff; g.Alo = p_wlo + woff;
        g.Bf = in; g.out = o;
        g.bias = bias; g.bnsc = bnsc; g.bnsh = bnsh; g.resid = resid;
        g.K = 4608; g.lda = 4608; g.ldo = H * W; g.Nn = H * W; g.H = H; g.W = W;
        g.relu = relu; g.ps = ps;
        k_tgemm<0, 1><<<dim3((H * W + 63) / 64, mblk, 1), 256, SMEM_DYN>>>(g);
    };

    conv(p_xs, W_HEAD, head_b, nullptr, nullptr, nullptr, p_h, 50, 50, 0, 0, 4);
    cudaMemcpyAsync(p_r, p_h, (size_t)512 * 2500 * sizeof(float),
                    cudaMemcpyDeviceToDevice, 0);
    for (int i = 0; i < 8; i++) {
        conv(p_r, W_BODY + (2 * i) * 2359296, body_b + (size_t)(2 * i) * 512,
             nullptr, nullptr, nullptr, p_tmp, 50, 50, 1, 0, 4);
        conv(p_tmp, W_BODY + (2 * i + 1) * 2359296, body_b + (size_t)(2 * i + 1) * 512,
             nullptr, nullptr, p_r, p_r, 50, 50, 0, 0, 4);
    }
    conv(p_r, W_BTAIL, btail_b, nullptr, nullptr, p_h, p_tmp, 50, 50, 0, 0, 4);
    conv(p_tmp, W_UP, up_b, nullptr, nullptr, nullptr, p_u, 50, 50, 0, 1, 16);
    conv(p_u, W_TAIL, tail_b, nullptr, nullptr, nullptr, p_y1, 100, 100, 0, 0, 4);

    // ---- classifier ----
    conv(p_y1, W_C1, nullptr, p_bn, p_bn + 512, nullptr, p_y2, 100, 100, 1, 0, 4);
    conv(p_y2, W_C2, nullptr, p_bn + 1024, p_bn + 1536, nullptr, p_y1, 100, 100, 1, 0, 4);
    k_c3<<<(60000 + 255) / 256, 256>>>(c3_w, c3_b, out);
}

// round 5
// speedup vs baseline: 1.5803x; 1.5803x over previous
#include <cuda_runtime.h>
#include <cuda_bf16.h>
#include <math.h>
#include <stdint.h>

// ============================================================
// Static device scratch
// ============================================================
__device__ float g_x[512 * 1024];        // attention state, C-major (c, tok)
__device__ float g_t[1024 * 512];        // V token-major (tok, vfeat)
__device__ float g_qkv[1024 * 1024];     // Q,K feature-major (feat, tok)
__device__ float g_attn[8 * 1024 * 1024];
__device__ float g_res[512 * 1024];      // attn out feature-major (feat, tok)
__device__ float g_xs[512 * 2500];
__device__ float g_h[512 * 2500];
__device__ float g_r[512 * 2500];
__device__ float g_tmp[512 * 2500];
__device__ float g_u[512 * 10000];
__device__ float g_y1[512 * 10000];
__device__ float g_y2[512 * 10000];
__device__ float g_bn[2048];

// conv weights presplit (hi+lo)
#define W_HEAD  0
#define W_BODY  2359296
#define W_BTAIL 40108032
#define W_UP    42467328
#define W_TAIL  51904512
#define W_C1    54263808
#define W_C2    56623104
#define W_TOTAL 58982400
__device__ __nv_bfloat16 g_whi[W_TOTAL];
__device__ __nv_bfloat16 g_wlo[W_TOTAL];
// attention weights presplit + transposed: qkv (8,1536,512), proj (8,512,512)
__device__ __nv_bfloat16 g_aqh[8 * 1536 * 512];
__device__ __nv_bfloat16 g_aql[8 * 1536 * 512];
__device__ __nv_bfloat16 g_aph[8 * 512 * 512];
__device__ __nv_bfloat16 g_apl[8 * 512 * 512];

// ============================================================
// Helpers
// ============================================================
__device__ __forceinline__ uint32_t smem_u32(const void* p) {
    uint32_t a;
    asm("{ .reg .u64 t; cvta.to.shared.u64 t, %1; cvt.u32.u64 %0, t; }"
        : "=r"(a) : "l"(p));
    return a;
}

__device__ __forceinline__ void ldsm4(uint32_t addr, uint32_t* r) {
    asm volatile("ldmatrix.sync.aligned.m8n8.x4.shared.b16 {%0,%1,%2,%3}, [%4];"
                 : "=r"(r[0]), "=r"(r[1]), "=r"(r[2]), "=r"(r[3]) : "r"(addr));
}

__device__ __forceinline__ void mma16816(float* d, const uint32_t* a,
                                         uint32_t b0, uint32_t b1) {
    asm volatile(
        "mma.sync.aligned.m16n8k16.row.col.f32.bf16.bf16.f32 "
        "{%0,%1,%2,%3}, {%4,%5,%6,%7}, {%8,%9}, {%0,%1,%2,%3};"
        : "+f"(d[0]), "+f"(d[1]), "+f"(d[2]), "+f"(d[3])
        : "r"(a[0]), "r"(a[1]), "r"(a[2]), "r"(a[3]), "r"(b0), "r"(b1));
}

__device__ __forceinline__ void split2(float v0, float v1, uint32_t& hp, uint32_t& lp) {
    __nv_bfloat16 h0 = __float2bfloat16(v0), h1 = __float2bfloat16(v1);
    __nv_bfloat16 l0 = __float2bfloat16(v0 - __bfloat162float(h0));
    __nv_bfloat16 l1 = __float2bfloat16(v1 - __bfloat162float(h1));
    hp = (uint32_t)__bfloat16_as_ushort(h0) | ((uint32_t)__bfloat16_as_ushort(h1) << 16);
    lp = (uint32_t)__bfloat16_as_ushort(l0) | ((uint32_t)__bfloat16_as_ushort(l1) << 16);
}

// ============================================================
// Weight prep kernels
// ============================================================
__global__ void k_wprep(const float* __restrict__ src, __nv_bfloat16* __restrict__ hi,
                        __nv_bfloat16* __restrict__ lo, int n) {
    int i = blockIdx.x * 256 + threadIdx.x;
    if (i >= n) return;
    float v = src[i];
    __nv_bfloat16 h = __float2bfloat16(v);
    hi[i] = h;
    lo[i] = __float2bfloat16(v - __bfloat162float(h));
}

// qkv_w (8,512,1536) -> transposed (8,1536,512)
__global__ void k_wtq(const float* __restrict__ src, __nv_bfloat16* __restrict__ hi,
                      __nv_bfloat16* __restrict__ lo) {
    int idx = blockIdx.x * 256 + threadIdx.x;
    if (idx >= 8 * 1536 * 512) return;
    int blk = idx / (1536 * 512), r = idx - blk * (1536 * 512);
    int f = r >> 9, c = r & 511;
    float v = src[(size_t)blk * 512 * 1536 + c * 1536 + f];
    __nv_bfloat16 h = __float2bfloat16(v);
    hi[idx] = h;
    lo[idx] = __float2bfloat16(v - __bfloat162float(h));
}

// proj_w (8,512,512) -> transposed
__global__ void k_wtp(const float* __restrict__ src, __nv_bfloat16* __restrict__ hi,
                      __nv_bfloat16* __restrict__ lo) {
    int idx = blockIdx.x * 256 + threadIdx.x;
    if (idx >= 8 * 512 * 512) return;
    int blk = idx / (512 * 512), r = idx - blk * (512 * 512);
    int f = r >> 9, c = r & 511;
    float v = src[(size_t)blk * 512 * 512 + c * 512 + f];
    __nv_bfloat16 h = __float2bfloat16(v);
    hi[idx] = h;
    lo[idx] = __float2bfloat16(v - __bfloat162float(h));
}

// ============================================================
// Shared smem layout (both GEMM kernels)
// ============================================================
#define PITCH 80
#define OFF_ALO (128 * PITCH)
#define OFF_BHI (2 * 128 * PITCH)
#define OFF_BLO (OFF_BHI + 64 * PITCH)
#define STAGE   (OFF_BLO + 64 * PITCH)   // 30720
#define SMEM_DYN (2 * STAGE)             // 61440

// ============================================================
// EXACT R3 conv kernel (proven): mma.sync implicit-GEMM conv3x3,
// 3-term bf16 split, tile M=128 x N=64, K=4608, chunks of 32.
// ============================================================
__global__ __launch_bounds__(256, 2)
void k_convtc(const float* __restrict__ in,
              const __nv_bfloat16* __restrict__ whi,
              const __nv_bfloat16* __restrict__ wlo,
              const float* __restrict__ bias,
              const float* __restrict__ bnsc, const float* __restrict__ bnsh,
              const float* __restrict__ resid, float* __restrict__ out,
              int H, int W, int relu, int ps) {
    extern __shared__ char sm[];
    const int P = H * W;
    const int K = 4608;
    int tid = threadIdx.x, wid = tid >> 5, lane = tid & 31;
    int n0 = blockIdx.x * 64, m0 = blockIdx.y * 128;
    uint32_t sb = smem_u32(sm);

    int arow = tid >> 1, aseg = tid & 1;
    const __nv_bfloat16* whp = whi + (size_t)(m0 + arow) * K + aseg * 16;
    const __nv_bfloat16* wlp = wlo + (size_t)(m0 + arow) * K + aseg * 16;
    uint32_t a_st = sb + arow * PITCH + aseg * 32;

    int bpix = tid & 63, bkg = tid >> 6;
    int pg = n0 + bpix;
    bool pval = pg < P;
    int pc = pval ? pg : 0;
    int py = pc / W, px = pc - py * W;
    uint32_t b_st = sb + OFF_BHI + bpix * PITCH + bkg * 16;

    uint4 rAh[2], rAl[2];
    float rB[8];

    auto load_gmem = [&](int ch) {
        int kk = ch << 5;
        rAh[0] = *(const uint4*)(whp + kk);
        rAh[1] = *(const uint4*)(whp + kk + 8);
        rAl[0] = *(const uint4*)(wlp + kk);
        rAl[1] = *(const uint4*)(wlp + kk + 8);
#pragma unroll
        for (int j = 0; j < 8; j++) {
            int k = kk + bkg * 8 + j;
            int ci = k / 9;
            int r9 = k - ci * 9;
            int ky = r9 / 3;
            int dy = ky - 1, dx = (r9 - ky * 3) - 1;
            int yy = py + dy, xx = px + dx;
            float v = 0.f;
            if (pval && (unsigned)yy < (unsigned)H && (unsigned)xx < (unsigned)W)
                v = in[(size_t)ci * P + yy * W + xx];
            rB[j] = v;
        }
    };

    auto store_smem = [&](int buf) {
        uint32_t bo = buf * STAGE;
        *(uint4*)(sm + (a_st - sb) + bo) = rAh[0];
        *(uint4*)(sm + (a_st - sb) + bo + 16) = rAh[1];
        *(uint4*)(sm + (a_st - sb) + bo + OFF_ALO) = rAl[0];
        *(uint4*)(sm + (a_st - sb) + bo + OFF_ALO + 16) = rAl[1];
#pragma unroll
        for (int j = 0; j < 8; j += 2) {
            uint32_t hp, lp;
            split2(rB[j], rB[j + 1], hp, lp);
            *(uint32_t*)(sm + (b_st - sb) + bo + j * 2) = hp;
            *(uint32_t*)(sm + (b_st - sb) + bo + (OFF_BLO - OFF_BHI) + j * 2) = lp;
        }
    };

    int warp_m = wid & 3, warp_n = wid >> 2;
    uint32_t a_ld = sb + (warp_m * 32 + (lane & 15)) * PITCH + (lane >> 4) * 16;
    uint32_t b_ld = sb + OFF_BHI + (warp_n * 32 + (lane & 15)) * PITCH + (lane >> 4) * 16;

    float acc[2][4][4];
#pragma unroll
    for (int i = 0; i < 2; i++)
#pragma unroll
        for (int j = 0; j < 4; j++)
#pragma unroll
            for (int e = 0; e < 4; e++) acc[i][j][e] = 0.f;

    load_gmem(0);
    store_smem(0);
    __syncthreads();

    for (int ch = 0; ch < 144; ch++) {
        if (ch < 143) load_gmem(ch + 1);
        uint32_t bo = (ch & 1) * STAGE;
#pragma unroll
        for (int ks = 0; ks < 2; ks++) {
            uint32_t Ah[2][4], Al[2][4], Bh[2][4], Bl[2][4];
#pragma unroll
            for (int mt = 0; mt < 2; mt++) {
                ldsm4(a_ld + bo + mt * (16 * PITCH) + ks * 32, Ah[mt]);
                ldsm4(a_ld + bo + OFF_ALO + mt * (16 * PITCH) + ks * 32, Al[mt]);
            }
#pragma unroll
            for (int gq = 0; gq < 2; gq++) {
                ldsm4(b_ld + bo + gq * (16 * PITCH) + ks * 32, Bh[gq]);
                ldsm4(b_ld + bo + (OFF_BLO - OFF_BHI) + gq * (16 * PITCH) + ks * 32, Bl[gq]);
            }
#pragma unroll
            for (int mt = 0; mt < 2; mt++)
#pragma unroll
                for (int nt = 0; nt < 4; nt++) {
                    int gq = nt >> 1, idx = nt & 1;
                    uint32_t bh0 = Bh[gq][idx], bh1 = Bh[gq][idx + 2];
                    uint32_t bl0 = Bl[gq][idx], bl1 = Bl[gq][idx + 2];
                    mma16816(acc[mt][nt], Ah[mt], bh0, bh1);
                    mma16816(acc[mt][nt], Ah[mt], bl0, bl1);
                    mma16816(acc[mt][nt], Al[mt], bh0, bh1);
                }
        }
        if (ch < 143) {
            store_smem((ch + 1) & 1);
            __syncthreads();
        }
    }

#pragma unroll
    for (int mt = 0; mt < 2; mt++) {
#pragma unroll
        for (int half = 0; half < 2; half++) {
            int co = m0 + warp_m * 32 + mt * 16 + (lane >> 2) + half * 8;
            float bv = bias ? bias[co] : 0.f;
            float sc = bnsc ? bnsc[co] : 1.f;
            float sh = bnsh ? bnsh[co] : 0.f;
#pragma unroll
            for (int nt = 0; nt < 4; nt++) {
#pragma unroll
                for (int e = 0; e < 2; e++) {
                    int p = n0 + warp_n * 32 + nt * 8 + (lane & 3) * 2 + e;
                    if (p >= P) continue;
                    float v = acc[mt][nt][half * 2 + e];
                    v += bv;
                    if (bnsc) v = v * sc + sh;
                    if (resid) v += resid[(size_t)co * P + p];
                    if (relu) v = fmaxf(v, 0.f);
                    if (ps) {
                        int c = co >> 2, ry = (co >> 1) & 1, rx = co & 1;
                        int yy = p / W, xx = p - (p / W) * W;
                        out[(size_t)c * (4 * P) + (size_t)(2 * yy + ry) * (2 * W) +
                            2 * xx + rx] = v;
                    } else {
                        out[(size_t)co * P + p] = v;
                    }
                }
            }
        }
    }
}

// ============================================================
// Attention tensor GEMM, same proven structure (register staging).
// AM: 0 = presplit bf16 [m][k]; 1 = fp32 [k][m]; 2 = fp32 [m][k]
// TRANS: 1 = store out[n][m] instead of out[m][n]
// ============================================================
template <int AM, int TRANS>
__global__ __launch_bounds__(256, 2)
void k_agemm(const __nv_bfloat16* __restrict__ Ahi, const __nv_bfloat16* __restrict__ Alo,
             const float* __restrict__ Af, const float* __restrict__ Bfg,
             float* __restrict__ outg, const float* __restrict__ bias,
             const float* __restrict__ resid,
             long aoz, long boz, long coz,
             int K, int lda, int ldb, int ldo, int Nn, float scale) {
    extern __shared__ char sm[];
    int tid = threadIdx.x, wid = tid >> 5, lane = tid & 31;
    int n0 = blockIdx.x * 64, m0 = blockIdx.y * 128, z = blockIdx.z;
    uint32_t sb = smem_u32(sm);
    int NCH = K >> 5;

    const float* Bf = Bfg + (size_t)z * boz;
    float* outp = outg + (size_t)z * coz;

    // A loader state
    int arow = tid >> 1, aseg = tid & 1;
    int krow = tid >> 3, mseg = tid & 7;
    const __nv_bfloat16 *whp = nullptr, *wlp = nullptr;
    const float* afp = nullptr;
    if constexpr (AM == 0) {
        whp = Ahi + (size_t)z * aoz + (size_t)(m0 + arow) * lda + aseg * 16;
        wlp = Alo + (size_t)z * aoz + (size_t)(m0 + arow) * lda + aseg * 16;
    } else if constexpr (AM == 1) {
        afp = Af + (size_t)z * aoz + (size_t)krow * lda + m0 + mseg * 16;
    } else {
        afp = Af + (size_t)z * aoz + (size_t)(m0 + arow) * lda + aseg * 16;
    }
    uint32_t a_off = arow * PITCH + aseg * 32;

    // B loader state
    int bpix = tid & 63, bkg = tid >> 6;
    uint32_t b_off = OFF_BHI + bpix * PITCH + bkg * 16;

    uint4 rAh[2], rAl[2];
    float rA[16];
    float rB[8];

    auto load_gmem = [&](int ch) {
        int kk = ch << 5;
        if constexpr (AM == 0) {
            rAh[0] = *(const uint4*)(whp + kk);
            rAh[1] = *(const uint4*)(whp + kk + 8);
            rAl[0] = *(const uint4*)(wlp + kk);
            rAl[1] = *(const uint4*)(wlp + kk + 8);
        } else if constexpr (AM == 1) {
            const float* p = afp + (size_t)kk * lda;
            *(float4*)(rA + 0) = *(const float4*)(p + 0);
            *(float4*)(rA + 4) = *(const float4*)(p + 4);
            *(float4*)(rA + 8) = *(const float4*)(p + 8);
            *(float4*)(rA + 12) = *(const float4*)(p + 12);
        } else {
            const float* p = afp + kk;
            *(float4*)(rA + 0) = *(const float4*)(p + 0);
            *(float4*)(rA + 4) = *(const float4*)(p + 4);
            *(float4*)(rA + 8) = *(const float4*)(p + 8);
            *(float4*)(rA + 12) = *(const float4*)(p + 12);
        }
#pragma unroll
        for (int j = 0; j < 8; j++)
            rB[j] = Bf[(size_t)(kk + bkg * 8 + j) * ldb + n0 + bpix];
    };

    auto store_smem = [&](int buf) {
        uint32_t bo = buf * STAGE;
        if constexpr (AM == 0) {
            *(uint4*)(sm + a_off + bo) = rAh[0];
            *(uint4*)(sm + a_off + bo + 16) = rAh[1];
            *(uint4*)(sm + a_off + bo + OFF_ALO) = rAl[0];
            *(uint4*)(sm + a_off + bo + OFF_ALO + 16) = rAl[1];
        } else if constexpr (AM == 1) {
#pragma unroll
            for (int j = 0; j < 16; j++) {
                float v = rA[j];
                __nv_bfloat16 h = __float2bfloat16(v);
                __nv_bfloat16 l = __float2bfloat16(v - __bfloat162float(h));
                uint32_t off = (mseg * 16 + j) * PITCH + krow * 2;
                *(__nv_bfloat16*)(sm + bo + off) = h;
                *(__nv_bfloat16*)(sm + bo + OFF_ALO + off) = l;
            }
        } else {
            uint32_t hp[8], lp[8];
#pragma unroll
            for (int j = 0; j < 8; j++) split2(rA[2 * j], rA[2 * j + 1], hp[j], lp[j]);
            *(uint4*)(sm + bo + a_off) = *(uint4*)hp;
            *(uint4*)(sm + bo + a_off + 16) = *(uint4*)(hp + 4);
            *(uint4*)(sm + bo + OFF_ALO + a_off) = *(uint4*)lp;
            *(uint4*)(sm + bo + OFF_ALO + a_off + 16) = *(uint4*)(lp + 4);
        }
#pragma unroll
        for (int j = 0; j < 8; j += 2) {
            uint32_t hp, lp;
            split2(rB[j], rB[j + 1], hp, lp);
            *(uint32_t*)(sm + (b_off - OFF_BHI) + OFF_BHI + bo + j * 2) = hp;
            *(uint32_t*)(sm + (b_off - OFF_BHI) + OFF_BLO + bo + j * 2) = lp;
        }
    };

    int warp_m = wid & 3, warp_n = wid >> 2;
    uint32_t a_ld = sb + (warp_m * 32 + (lane & 15)) * PITCH + (lane >> 4) * 16;
    uint32_t b_ld = sb + OFF_BHI + (warp_n * 32 + (lane & 15)) * PITCH + (lane >> 4) * 16;

    float acc[2][4][4];
#pragma unroll
    for (int i = 0; i < 2; i++)
#pragma unroll
        for (int j = 0; j < 4; j++)
#pragma unroll
            for (int e = 0; e < 4; e++) acc[i][j][e] = 0.f;

    load_gmem(0);
    store_smem(0);
    __syncthreads();

    for (int ch = 0; ch < NCH; ch++) {
        if (ch + 1 < NCH) load_gmem(ch + 1);
        uint32_t bo = (ch & 1) * STAGE;
#pragma unroll
        for (int ks = 0; ks < 2; ks++) {
            uint32_t Ah[2][4], Al[2][4], Bh[2][4], Bl[2][4];
#pragma unroll
            for (int mt = 0; mt < 2; mt++) {
                ldsm4(a_ld + bo + mt * (16 * PITCH) + ks * 32, Ah[mt]);
                ldsm4(a_ld + bo + OFF_ALO + mt * (16 * PITCH) + ks * 32, Al[mt]);
            }
#pragma unroll
            for (int gq = 0; gq < 2; gq++) {
                ldsm4(b_ld + bo + gq * (16 * PITCH) + ks * 32, Bh[gq]);
                ldsm4(b_ld + bo + (OFF_BLO - OFF_BHI) + gq * (16 * PITCH) + ks * 32, Bl[gq]);
            }
#pragma unroll
            for (int mt = 0; mt < 2; mt++)
#pragma unroll
                for (int nt = 0; nt < 4; nt++) {
                    int gq = nt >> 1, idx = nt & 1;
                    uint32_t bh0 = Bh[gq][idx], bh1 = Bh[gq][idx + 2];
                    uint32_t bl0 = Bl[gq][idx], bl1 = Bl[gq][idx + 2];
                    mma16816(acc[mt][nt], Ah[mt], bh0, bh1);
                    mma16816(acc[mt][nt], Ah[mt], bl0, bl1);
                    mma16816(acc[mt][nt], Al[mt], bh0, bh1);
                }
        }
        if (ch + 1 < NCH) {
            store_smem((ch + 1) & 1);
            __syncthreads();
        }
    }

#pragma unroll
    for (int mt = 0; mt < 2; mt++) {
#pragma unroll
        for (int half = 0; half < 2; half++) {
            int co = m0 + warp_m * 32 + mt * 16 + (lane >> 2) + half * 8;
            float bv = bias ? bias[co] : 0.f;
#pragma unroll
            for (int nt = 0; nt < 4; nt++) {
#pragma unroll
                for (int e = 0; e < 2; e++) {
                    int p = n0 + warp_n * 32 + nt * 8 + (lane & 3) * 2 + e;
                    if (p >= Nn) continue;
                    float v = acc[mt][nt][half * 2 + e] * scale + bv;
                    if (resid) v += resid[(size_t)co * ldo + p];
                    if (TRANS) outp[(size_t)p * ldo + co] = v;
                    else outp[(size_t)co * ldo + p] = v;
                }
            }
        }
    }
}

// ============================================================
// Softmax (scale pre-applied by scores epilogue)
// ============================================================
__global__ __launch_bounds__(256)
void k_softmax() {
    float* p = g_attn + (size_t)blockIdx.x * 1024;
    int tid = threadIdx.x;
    float4 v = *(float4*)(p + tid * 4);
    float mx = fmaxf(fmaxf(v.x, v.y), fmaxf(v.z, v.w));
#pragma unroll
    for (int o = 16; o > 0; o >>= 1) mx = fmaxf(mx, __shfl_xor_sync(0xffffffffu, mx, o));
    __shared__ float smx[8], ssm[8];
    if ((tid & 31) == 0) smx[tid >> 5] = mx;
    __syncthreads();
    mx = smx[0];
#pragma unroll
    for (int i = 1; i < 8; i++) mx = fmaxf(mx, smx[i]);
    float e0 = expf(v.x - mx), e1 = expf(v.y - mx), e2 = expf(v.z - mx), e3 = expf(v.w - mx);
    float s = e0 + e1 + e2 + e3;
#pragma unroll
    for (int o = 16; o > 0; o >>= 1) s += __shfl_xor_sync(0xffffffffu, s, o);
    if ((tid & 31) == 0) ssm[tid >> 5] = s;
    __syncthreads();
    s = ssm[0] + ssm[1] + ssm[2] + ssm[3] + ssm[4] + ssm[5] + ssm[6] + ssm[7];
    float inv = 1.f / s;
    *(float4*)(p + tid * 4) = make_float4(e0 * inv, e1 * inv, e2 * inv, e3 * inv);
}

// ============================================================
// Grid sample, BN fold, c3
// ============================================================
__device__ __forceinline__ int map_idx(int o, int size, bool* valid) {
    float vv = -49.f + 2.f * (float)o;
    float gg = (vv + 51.2f) / 102.4f * 2.f - 1.f;
    float f = ((gg + 1.f) * (float)size - 1.f) * 0.5f;
    int ii = (int)rintf(f);
    *valid = (ii >= 0) && (ii < size);
    return min(max(ii, 0), size - 1);
}

__global__ void k_gridsample() {
    int idx = blockIdx.x * 256 + threadIdx.x;
    if (idx >= 512 * 2500) return;
    int c = idx / 2500, p = idx - c * 2500;
    int oy = p / 50, ox = p - oy * 50;
    bool vy, vx;
    int iy = map_idx(oy, 32, &vy);
    int ix = map_idx(ox, 32, &vx);
    g_xs[idx] = (vy && vx) ? g_x[(size_t)c * 1024 + iy * 32 + ix] : 0.f;
}

__global__ void k_bnprep(const float* g1, const float* b1, const float* m1, const float* v1,
                         const float* g2, const float* b2, const float* m2, const float* v2) {
    int c = blockIdx.x * 256 + threadIdx.x;
    if (c >= 512) return;
    float s1 = g1[c] / sqrtf(v1[c] + 1e-5f);
    g_bn[c] = s1;
    g_bn[512 + c] = b1[c] - m1[c] * s1;
    float s2 = g2[c] / sqrtf(v2[c] + 1e-5f);
    g_bn[1024 + c] = s2;
    g_bn[1536 + c] = b2[c] - m2[c] * s2;
}

__global__ void k_c3(const float* __restrict__ w, const float* __restrict__ b,
                     float* __restrict__ out) {
    int idx = blockIdx.x * 256 + threadIdx.x;
    if (idx >= 60000) return;
    int cls = idx / 10000, p = idx - cls * 10000;
    const float* wr = w + cls * 512;
    float s = b[cls];
#pragma unroll 4
    for (int c = 0; c < 512; c++) s += g_y1[(size_t)c * 10000 + p] * wr[c];
    out[idx] = 1.f / (1.f + expf(-s));
}

// ============================================================
// Host orchestration
// ============================================================
extern "C" void kernel_launch(void* const* d_in, const int* in_sizes, int n_in,
                              void* d_out, int out_size) {
    const float* x       = (const float*)d_in[0];
    const float* qkv_w   = (const float*)d_in[1];
    const float* proj_w  = (const float*)d_in[2];
    const float* proj_b  = (const float*)d_in[3];
    const float* head_w  = (const float*)d_in[4];
    const float* head_b  = (const float*)d_in[5];
    const float* body_w  = (const float*)d_in[6];
    const float* body_b  = (const float*)d_in[7];
    const float* btail_w = (const float*)d_in[8];
    const float* btail_b = (const float*)d_in[9];
    const float* up_w    = (const float*)d_in[10];
    const float* up_b    = (const float*)d_in[11];
    const float* tail_w  = (const float*)d_in[12];
    const float* tail_b  = (const float*)d_in[13];
    const float* c1_w    = (const float*)d_in[14];
    const float* bn1_g   = (const float*)d_in[15];
    const float* bn1_b   = (const float*)d_in[16];
    const float* bn1_m   = (const float*)d_in[17];
    const float* bn1_v   = (const float*)d_in[18];
    const float* c2_w    = (const float*)d_in[19];
    const float* bn2_g   = (const float*)d_in[20];
    const float* bn2_b   = (const float*)d_in[21];
    const float* bn2_m   = (const float*)d_in[22];
    const float* bn2_v   = (const float*)d_in[23];
    const float* c3_w    = (const float*)d_in[24];
    const float* c3_b    = (const float*)d_in[25];
    float* out = (float*)d_out;

    float *p_x, *p_t, *p_qkv, *p_attn, *p_res, *p_xs, *p_h, *p_r, *p_tmp, *p_u, *p_y1, *p_y2, *p_bn;
    __nv_bfloat16 *p_whi, *p_wlo, *p_aqh, *p_aql, *p_aph, *p_apl;
    cudaGetSymbolAddress((void**)&p_x, g_x);
    cudaGetSymbolAddress((void**)&p_t, g_t);
    cudaGetSymbolAddress((void**)&p_qkv, g_qkv);
    cudaGetSymbolAddress((void**)&p_attn, g_attn);
    cudaGetSymbolAddress((void**)&p_res, g_res);
    cudaGetSymbolAddress((void**)&p_xs, g_xs);
    cudaGetSymbolAddress((void**)&p_h, g_h);
    cudaGetSymbolAddress((void**)&p_r, g_r);
    cudaGetSymbolAddress((void**)&p_tmp, g_tmp);
    cudaGetSymbolAddress((void**)&p_u, g_u);
    cudaGetSymbolAddress((void**)&p_y1, g_y1);
    cudaGetSymbolAddress((void**)&p_y2, g_y2);
    cudaGetSymbolAddress((void**)&p_bn, g_bn);
    cudaGetSymbolAddress((void**)&p_whi, g_whi);
    cudaGetSymbolAddress((void**)&p_wlo, g_wlo);
    cudaGetSymbolAddress((void**)&p_aqh, g_aqh);
    cudaGetSymbolAddress((void**)&p_aql, g_aql);
    cudaGetSymbolAddress((void**)&p_aph, g_aph);
    cudaGetSymbolAddress((void**)&p_apl, g_apl);

    cudaFuncSetAttribute(k_convtc, cudaFuncAttributeMaxDynamicSharedMemorySize, SMEM_DYN);
    cudaFuncSetAttribute(k_agemm<0, 0>, cudaFuncAttributeMaxDynamicSharedMemorySize, SMEM_DYN);
    cudaFuncSetAttribute(k_agemm<0, 1>, cudaFuncAttributeMaxDynamicSharedMemorySize, SMEM_DYN);
    cudaFuncSetAttribute(k_agemm<1, 0>, cudaFuncAttributeMaxDynamicSharedMemorySize, SMEM_DYN);
    cudaFuncSetAttribute(k_agemm<2, 1>, cudaFuncAttributeMaxDynamicSharedMemorySize, SMEM_DYN);

    cudaMemcpyAsync(p_x, x, (size_t)512 * 1024 * sizeof(float),
                    cudaMemcpyDeviceToDevice, 0);

    // ---- weight prep ----
    {
        struct { const float* s; int off; int n; } regs[7] = {
            {head_w,  W_HEAD,  2359296},
            {body_w,  W_BODY,  37748736},
            {btail_w, W_BTAIL, 2359296},
            {up_w,    W_UP,    9437184},
            {tail_w,  W_TAIL,  2359296},
            {c1_w,    W_C1,    2359296},
            {c2_w,    W_C2,    2359296},
        };
        for (int i = 0; i < 7; i++)
            k_wprep<<<(regs[i].n + 255) / 256, 256>>>(regs[i].s, p_whi + regs[i].off,
                                                      p_wlo + regs[i].off, regs[i].n);
        k_wtq<<<(8 * 1536 * 512 + 255) / 256, 256>>>(qkv_w, p_aqh, p_aql);
        k_wtp<<<(8 * 512 * 512 + 255) / 256, 256>>>(proj_w, p_aph, p_apl);
    }

    const float scale = 0.044194173824159216f;  // 512^-0.5

    // ---- 8 self-attention blocks (tensor cores, R3-style loaders) ----
    for (int i = 0; i < 8; i++) {
        // Q,K: M=1024 feats x N=1024 tok, K=512, out feature-major g_qkv
        k_agemm<0, 0><<<dim3(16, 8, 1), 256, SMEM_DYN>>>(
            p_aqh + (size_t)i * 1536 * 512, p_aql + (size_t)i * 1536 * 512,
            nullptr, p_x, p_qkv, nullptr, nullptr,
            0, 0, 0, 512, 512, 1024, 1024, 1024, 1.f);
        // V: M=512 x N=1024, trans-store token-major g_t
        k_agemm<0, 1><<<dim3(16, 4, 1), 256, SMEM_DYN>>>(
            p_aqh + (size_t)i * 1536 * 512 + (size_t)1024 * 512,
            p_aql + (size_t)i * 1536 * 512 + (size_t)1024 * 512,
            nullptr, p_x, p_t, nullptr, nullptr,
            0, 0, 0, 512, 512, 1024, 512, 1024, 1.f);
        // scores: per head S = Q^T K * scale
        k_agemm<1, 0><<<dim3(16, 8, 8), 256, SMEM_DYN>>>(
            nullptr, nullptr, p_qkv, p_qkv + (size_t)512 * 1024, p_attn,
            nullptr, nullptr,
            64 * 1024, 64 * 1024, 1l << 20, 64, 1024, 1024, 1024, 1024, scale);
        k_softmax<<<8192, 256>>>();
        // AV: per head O = P V, trans-store feature-major g_res
        k_agemm<2, 1><<<dim3(1, 8, 8), 256, SMEM_DYN>>>(
            nullptr, nullptr, p_attn, p_t, p_res, nullptr, nullptr,
            1l << 20, 64, 64 * 1024, 1024, 1024, 512, 1024, 64, 1.f);
        // proj: M=512 x N=1024 + bias + residual accumulate into g_x
        k_agemm<0, 0><<<dim3(16, 4, 1), 256, SMEM_DYN>>>(
            p_aph + (size_t)i * 512 * 512, p_apl + (size_t)i * 512 * 512,
            nullptr, p_res, p_x, proj_b + (size_t)i * 512, p_x,
            0, 0, 0, 512, 512, 1024, 1024, 1024, 1.f);
    }

    // ---- grid transform + BN fold ----
    k_gridsample<<<(512 * 2500 + 255) / 256, 256>>>();
    k_bnprep<<<2, 256>>>(bn1_g, bn1_b, bn1_m, bn1_v, bn2_g, bn2_b, bn2_m, bn2_v);

    // ---- EDSR upsampler (exact R3 conv kernel) ----
    dim3 g50(40, 4);
    k_convtc<<<g50, 256, SMEM_DYN>>>(p_xs, p_whi + W_HEAD, p_wlo + W_HEAD, head_b,
                                     nullptr, nullptr, nullptr, p_h, 50, 50, 0, 0);
    cudaMemcpyAsync(p_r, p_h, (size_t)512 * 2500 * sizeof(float),
                    cudaMemcpyDeviceToDevice, 0);
    for (int i = 0; i < 8; i++) {
        int o0 = W_BODY + (2 * i) * 2359296;
        int o1 = W_BODY + (2 * i + 1) * 2359296;
        k_convtc<<<g50, 256, SMEM_DYN>>>(p_r, p_whi + o0, p_wlo + o0,
                                         body_b + (size_t)(2 * i) * 512,
                                         nullptr, nullptr, nullptr, p_tmp, 50, 50, 1, 0);
        k_convtc<<<g50, 256, SMEM_DYN>>>(p_tmp, p_whi + o1, p_wlo + o1,
                                         body_b + (size_t)(2 * i + 1) * 512,
                                         nullptr, nullptr, p_r, p_r, 50, 50, 0, 0);
    }
    k_convtc<<<g50, 256, SMEM_DYN>>>(p_r, p_whi + W_BTAIL, p_wlo + W_BTAIL, btail_b,
                                     nullptr, nullptr, p_h, p_tmp, 50, 50, 0, 0);
    k_convtc<<<dim3(40, 16), 256, SMEM_DYN>>>(p_tmp, p_whi + W_UP, p_wlo + W_UP, up_b,
                                              nullptr, nullptr, nullptr, p_u, 50, 50, 0, 1);
    dim3 g100(157, 4);
    k_convtc<<<g100, 256, SMEM_DYN>>>(p_u, p_whi + W_TAIL, p_wlo + W_TAIL, tail_b,
                                      nullptr, nullptr, nullptr, p_y1, 100, 100, 0, 0);

    // ---- classifier ----
    k_convtc<<<g100, 256, SMEM_DYN>>>(p_y1, p_whi + W_C1, p_wlo + W_C1, nullptr,
                                      p_bn, p_bn + 512, nullptr, p_y2, 100, 100, 1, 0);
    k_convtc<<<g100, 256, SMEM_DYN>>>(p_y2, p_whi + W_C2, p_wlo + W_C2, nullptr,
                                      p_bn + 1024, p_bn + 1536, nullptr, p_y1, 100, 100, 1, 0);
    k_c3<<<(60000 + 255) / 256, 256>>>(c3_w, c3_b, out);
}

// round 9
// speedup vs baseline: 1.7472x; 1.1056x over previous
#include <cuda_runtime.h>
#include <cuda_bf16.h>
#include <math.h>
#include <stdint.h>

// ============================================================
// Static device scratch
// ============================================================
__device__ float g_x[512 * 1024];        // attention state, C-major
__device__ float g_t[1024 * 512];        // V token-major
__device__ float g_qkv[1024 * 1024];     // Q,K feature-major
__device__ float g_attn[8 * 1024 * 1024];
__device__ float g_res[512 * 1024];      // attn out feature-major
// packed bf16x2 activation planes (hi in low16, lo in high16)
__device__ uint32_t g_xs[512 * 2500];
__device__ uint32_t g_h[512 * 2500];
__device__ uint32_t g_r[512 * 2500];
__device__ uint32_t g_tmp[512 * 2500];
__device__ uint32_t g_u[512 * 10000];
__device__ uint32_t g_y1[512 * 10000];
__device__ uint32_t g_y2[512 * 10000];
__device__ float g_bn[2048];

// conv weights presplit (hi+lo)
#define W_HEAD  0
#define W_BODY  2359296
#define W_BTAIL 40108032
#define W_UP    42467328
#define W_TAIL  51904512
#define W_C1    54263808
#define W_C2    56623104
#define W_TOTAL 58982400
__device__ __nv_bfloat16 g_whi[W_TOTAL];
__device__ __nv_bfloat16 g_wlo[W_TOTAL];
// attention weights presplit + transposed
__device__ __nv_bfloat16 g_aqh[8 * 1536 * 512];
__device__ __nv_bfloat16 g_aql[8 * 1536 * 512];
__device__ __nv_bfloat16 g_aph[8 * 512 * 512];
__device__ __nv_bfloat16 g_apl[8 * 512 * 512];

// ============================================================
// Helpers
// ============================================================
__device__ __forceinline__ uint32_t smem_u32(const void* p) {
    uint32_t a;
    asm("{ .reg .u64 t; cvta.to.shared.u64 t, %1; cvt.u32.u64 %0, t; }"
        : "=r"(a) : "l"(p));
    return a;
}

__device__ __forceinline__ void cpasync16(uint32_t dst, const void* src) {
    asm volatile("cp.async.ca.shared.global [%0], [%1], 16;" :: "r"(dst), "l"(src));
}
#define CP_COMMIT asm volatile("cp.async.commit_group;" ::: "memory")
#define CP_WAIT0  asm volatile("cp.async.wait_group 0;" ::: "memory")

__device__ __forceinline__ void ldsm4(uint32_t addr, uint32_t* r) {
    asm volatile("ldmatrix.sync.aligned.m8n8.x4.shared.b16 {%0,%1,%2,%3}, [%4];"
                 : "=r"(r[0]), "=r"(r[1]), "=r"(r[2]), "=r"(r[3]) : "r"(addr));
}

__device__ __forceinline__ void mma16816(float* d, const uint32_t* a,
                                         uint32_t b0, uint32_t b1) {
    asm volatile(
        "mma.sync.aligned.m16n8k16.row.col.f32.bf16.bf16.f32 "
        "{%0,%1,%2,%3}, {%4,%5,%6,%7}, {%8,%9}, {%0,%1,%2,%3};"
        : "+f"(d[0]), "+f"(d[1]), "+f"(d[2]), "+f"(d[3])
        : "r"(a[0]), "r"(a[1]), "r"(a[2]), "r"(a[3]), "r"(b0), "r"(b1));
}

__device__ __forceinline__ void split2(float v0, float v1, uint32_t& hp, uint32_t& lp) {
    __nv_bfloat16 h0 = __float2bfloat16(v0), h1 = __float2bfloat16(v1);
    __nv_bfloat16 l0 = __float2bfloat16(v0 - __bfloat162float(h0));
    __nv_bfloat16 l1 = __float2bfloat16(v1 - __bfloat162float(h1));
    hp = (uint32_t)__bfloat16_as_ushort(h0) | ((uint32_t)__bfloat16_as_ushort(h1) << 16);
    lp = (uint32_t)__bfloat16_as_ushort(l0) | ((uint32_t)__bfloat16_as_ushort(l1) << 16);
}

__device__ __forceinline__ uint32_t packbf(float v) {
    __nv_bfloat16 h = __float2bfloat16(v);
    __nv_bfloat16 l = __float2bfloat16(v - __bfloat162float(h));
    return (uint32_t)__bfloat16_as_ushort(h) | ((uint32_t)__bfloat16_as_ushort(l) << 16);
}

__device__ __forceinline__ float unpackbf(uint32_t p) {
    return __bfloat162float(__ushort_as_bfloat16((unsigned short)(p & 0xffff))) +
           __bfloat162float(__ushort_as_bfloat16((unsigned short)(p >> 16)));
}

// ============================================================
// Weight prep kernels
// ============================================================
__global__ void k_wprep(const float* __restrict__ src, __nv_bfloat16* __restrict__ hi,
                        __nv_bfloat16* __restrict__ lo, int n) {
    int i = blockIdx.x * 256 + threadIdx.x;
    if (i >= n) return;
    float v = src[i];
    __nv_bfloat16 h = __float2bfloat16(v);
    hi[i] = h;
    lo[i] = __float2bfloat16(v - __bfloat162float(h));
}

__global__ void k_wtq(const float* __restrict__ src, __nv_bfloat16* __restrict__ hi,
                      __nv_bfloat16* __restrict__ lo) {
    int idx = blockIdx.x * 256 + threadIdx.x;
    if (idx >= 8 * 1536 * 512) return;
    int blk = idx / (1536 * 512), r = idx - blk * (1536 * 512);
    int f = r >> 9, c = r & 511;
    float v = src[(size_t)blk * 512 * 1536 + c * 1536 + f];
    __nv_bfloat16 h = __float2bfloat16(v);
    hi[idx] = h;
    lo[idx] = __float2bfloat16(v - __bfloat162float(h));
}

__global__ void k_wtp(const float* __restrict__ src, __nv_bfloat16* __restrict__ hi,
                      __nv_bfloat16* __restrict__ lo) {
    int idx = blockIdx.x * 256 + threadIdx.x;
    if (idx >= 8 * 512 * 512) return;
    int blk = idx / (512 * 512), r = idx - blk * (512 * 512);
    int f = r >> 9, c = r & 511;
    float v = src[(size_t)blk * 512 * 512 + c * 512 + f];
    __nv_bfloat16 h = __float2bfloat16(v);
    hi[idx] = h;
    lo[idx] = __float2bfloat16(v - __bfloat162float(h));
}

// ============================================================
// Shared smem layout
// ============================================================
#define PITCH 80
#define OFF_ALO (128 * PITCH)
#define OFF_BHI (2 * 128 * PITCH)
#define OFF_BLO (OFF_BHI + 64 * PITCH)
#define STAGE   (OFF_BLO + 64 * PITCH)   // 30720
#define SMEM_DYN (2 * STAGE)             // 61440

// ============================================================
// Conv3x3 kernel: R3 skeleton + packed-bf16x2 B input + cp.async A.
// Tile M=128 x N=64 px, K=4608, chunks of 32, double-buffered.
// ============================================================
__global__ __launch_bounds__(256, 2)
void k_convtc(const uint32_t* __restrict__ in,
              const __nv_bfloat16* __restrict__ whi,
              const __nv_bfloat16* __restrict__ wlo,
              const float* __restrict__ bias,
              const float* __restrict__ bnsc, const float* __restrict__ bnsh,
              const uint32_t* __restrict__ resid, uint32_t* __restrict__ out,
              int H, int W, int relu, int ps) {
    extern __shared__ char sm[];
    const int P = H * W;
    const int K = 4608;
    int tid = threadIdx.x, wid = tid >> 5, lane = tid & 31;
    int n0 = blockIdx.x * 64, m0 = blockIdx.y * 128;
    uint32_t sb = smem_u32(sm);

    // A: cp.async of presplit bf16 weights
    int arow = tid >> 1, aseg = tid & 1;
    const __nv_bfloat16* whp = whi + (size_t)(m0 + arow) * K + aseg * 16;
    const __nv_bfloat16* wlp = wlo + (size_t)(m0 + arow) * K + aseg * 16;
    uint32_t a_off = arow * PITCH + aseg * 32;

    // B: 1 pixel per thread, 8 packed k-values
    int bpix = tid & 63, bkg = tid >> 6;
    int pg = n0 + bpix;
    bool pval = pg < P;
    int pc = pval ? pg : 0;
    int py = pc / W, px = pc - py * W;
    uint32_t b_off = OFF_BHI + bpix * PITCH + bkg * 16;

    uint32_t rBp[8];

    auto a_issue = [&](int ch, int buf) {
        int kk = ch << 5;
        uint32_t d0 = sb + a_off + buf * STAGE;
        cpasync16(d0, whp + kk);
        cpasync16(d0 + 16, whp + kk + 8);
        cpasync16(d0 + OFF_ALO, wlp + kk);
        cpasync16(d0 + OFF_ALO + 16, wlp + kk + 8);
        CP_COMMIT;
    };

    auto b_load = [&](int ch) {
        int kk = ch << 5;
#pragma unroll
        for (int j = 0; j < 8; j++) {
            int k = kk + bkg * 8 + j;
            int ci = k / 9;
            int r9 = k - ci * 9;
            int ky = r9 / 3;
            int dy = ky - 1, dx = (r9 - ky * 3) - 1;
            int yy = py + dy, xx = px + dx;
            uint32_t v = 0;
            if (pval && (unsigned)yy < (unsigned)H && (unsigned)xx < (unsigned)W)
                v = in[(size_t)ci * P + yy * W + xx];
            rBp[j] = v;
        }
    };

    auto b_store = [&](int buf) {
        uint32_t bo = buf * STAGE;
#pragma unroll
        for (int j = 0; j < 8; j += 2) {
            uint32_t hp = __byte_perm(rBp[j], rBp[j + 1], 0x5410);
            uint32_t lp = __byte_perm(rBp[j], rBp[j + 1], 0x7632);
            *(uint32_t*)(sm + (b_off - OFF_BHI) + OFF_BHI + bo + j * 2) = hp;
            *(uint32_t*)(sm + (b_off - OFF_BHI) + OFF_BLO + bo + j * 2) = lp;
        }
    };

    int warp_m = wid & 3, warp_n = wid >> 2;
    uint32_t a_ld = sb + (warp_m * 32 + (lane & 15)) * PITCH + (lane >> 4) * 16;
    uint32_t b_ld = sb + OFF_BHI + (warp_n * 32 + (lane & 15)) * PITCH + (lane >> 4) * 16;

    float acc[2][4][4];
#pragma unroll
    for (int i = 0; i < 2; i++)
#pragma unroll
        for (int j = 0; j < 4; j++)
#pragma unroll
            for (int e = 0; e < 4; e++) acc[i][j][e] = 0.f;

    // prologue
    a_issue(0, 0);
    b_load(0);
    b_store(0);
    CP_WAIT0;
    __syncthreads();

    for (int ch = 0; ch < 144; ch++) {
        if (ch < 143) {
            a_issue(ch + 1, (ch + 1) & 1);
            b_load(ch + 1);
        }
        uint32_t bo = (ch & 1) * STAGE;
#pragma unroll
        for (int ks = 0; ks < 2; ks++) {
            uint32_t Ah[2][4], Al[2][4], Bh[2][4], Bl[2][4];
#pragma unroll
            for (int mt = 0; mt < 2; mt++) {
                ldsm4(a_ld + bo + mt * (16 * PITCH) + ks * 32, Ah[mt]);
                ldsm4(a_ld + bo + OFF_ALO + mt * (16 * PITCH) + ks * 32, Al[mt]);
            }
#pragma unroll
            for (int gq = 0; gq < 2; gq++) {
                ldsm4(b_ld + bo + gq * (16 * PITCH) + ks * 32, Bh[gq]);
                ldsm4(b_ld + bo + (OFF_BLO - OFF_BHI) + gq * (16 * PITCH) + ks * 32, Bl[gq]);
            }
#pragma unroll
            for (int mt = 0; mt < 2; mt++)
#pragma unroll
                for (int nt = 0; nt < 4; nt++) {
                    int gq = nt >> 1, idx = nt & 1;
                    uint32_t bh0 = Bh[gq][idx], bh1 = Bh[gq][idx + 2];
                    uint32_t bl0 = Bl[gq][idx], bl1 = Bl[gq][idx + 2];
                    mma16816(acc[mt][nt], Ah[mt], bh0, bh1);
                    mma16816(acc[mt][nt], Ah[mt], bl0, bl1);
                    mma16816(acc[mt][nt], Al[mt], bh0, bh1);
                }
        }
        if (ch < 143) {
            b_store((ch + 1) & 1);
            CP_WAIT0;
            __syncthreads();
        }
    }

    // epilogue: pack outputs to bf16x2
#pragma unroll
    for (int mt = 0; mt < 2; mt++) {
#pragma unroll
        for (int half = 0; half < 2; half++) {
            int co = m0 + warp_m * 32 + mt * 16 + (lane >> 2) + half * 8;
            float bv = bias ? bias[co] : 0.f;
            float sc = bnsc ? bnsc[co] : 1.f;
            float sh = bnsh ? bnsh[co] : 0.f;
#pragma unroll
            for (int nt = 0; nt < 4; nt++) {
#pragma unroll
                for (int e = 0; e < 2; e++) {
                    int p = n0 + warp_n * 32 + nt * 8 + (lane & 3) * 2 + e;
                    if (p >= P) continue;
                    float v = acc[mt][nt][half * 2 + e];
                    v += bv;
                    if (bnsc) v = v * sc + sh;
                    if (resid) v += unpackbf(resid[(size_t)co * P + p]);
                    if (relu) v = fmaxf(v, 0.f);
                    uint32_t pk = packbf(v);
                    if (ps) {
                        int c = co >> 2, ry = (co >> 1) & 1, rx = co & 1;
                        int yy = p / W, xx = p - (p / W) * W;
                        out[(size_t)c * (4 * P) + (size_t)(2 * yy + ry) * (2 * W) +
                            2 * xx + rx] = pk;
                    } else {
                        out[(size_t)co * P + p] = pk;
                    }
                }
            }
        }
    }
}

// ============================================================
// Attention tensor GEMM (unchanged from R5)
// ============================================================
template <int AM, int TRANS>
__global__ __launch_bounds__(256, 2)
void k_agemm(const __nv_bfloat16* __restrict__ Ahi, const __nv_bfloat16* __restrict__ Alo,
             const float* __restrict__ Af, const float* __restrict__ Bfg,
             float* __restrict__ outg, const float* __restrict__ bias,
             const float* __restrict__ resid,
             long aoz, long boz, long coz,
             int K, int lda, int ldb, int ldo, int Nn, float scale) {
    extern __shared__ char sm[];
    int tid = threadIdx.x, wid = tid >> 5, lane = tid & 31;
    int n0 = blockIdx.x * 64, m0 = blockIdx.y * 128, z = blockIdx.z;
    uint32_t sb = smem_u32(sm);
    int NCH = K >> 5;

    const float* Bf = Bfg + (size_t)z * boz;
    float* outp = outg + (size_t)z * coz;

    int arow = tid >> 1, aseg = tid & 1;
    int krow = tid >> 3, mseg = tid & 7;
    const __nv_bfloat16 *whp = nullptr, *wlp = nullptr;
    const float* afp = nullptr;
    if constexpr (AM == 0) {
        whp = Ahi + (size_t)z * aoz + (size_t)(m0 + arow) * lda + aseg * 16;
        wlp = Alo + (size_t)z * aoz + (size_t)(m0 + arow) * lda + aseg * 16;
    } else if constexpr (AM == 1) {
        afp = Af + (size_t)z * aoz + (size_t)krow * lda + m0 + mseg * 16;
    } else {
        afp = Af + (size_t)z * aoz + (size_t)(m0 + arow) * lda + aseg * 16;
    }
    uint32_t a_off = arow * PITCH + aseg * 32;

    int bpix = tid & 63, bkg = tid >> 6;
    uint32_t b_off = OFF_BHI + bpix * PITCH + bkg * 16;

    uint4 rAh[2], rAl[2];
    float rA[16];
    float rB[8];

    auto load_gmem = [&](int ch) {
        int kk = ch << 5;
        if constexpr (AM == 0) {
            rAh[0] = *(const uint4*)(whp + kk);
            rAh[1] = *(const uint4*)(whp + kk + 8);
            rAl[0] = *(const uint4*)(wlp + kk);
            rAl[1] = *(const uint4*)(wlp + kk + 8);
        } else if constexpr (AM == 1) {
            const float* p = afp + (size_t)kk * lda;
            *(float4*)(rA + 0) = *(const float4*)(p + 0);
            *(float4*)(rA + 4) = *(const float4*)(p + 4);
            *(float4*)(rA + 8) = *(const float4*)(p + 8);
            *(float4*)(rA + 12) = *(const float4*)(p + 12);
        } else {
            const float* p = afp + kk;
            *(float4*)(rA + 0) = *(const float4*)(p + 0);
            *(float4*)(rA + 4) = *(const float4*)(p + 4);
            *(float4*)(rA + 8) = *(const float4*)(p + 8);
            *(float4*)(rA + 12) = *(const float4*)(p + 12);
        }
#pragma unroll
        for (int j = 0; j < 8; j++)
            rB[j] = Bf[(size_t)(kk + bkg * 8 + j) * ldb + n0 + bpix];
    };

    auto store_smem = [&](int buf) {
        uint32_t bo = buf * STAGE;
        if constexpr (AM == 0) {
            *(uint4*)(sm + a_off + bo) = rAh[0];
            *(uint4*)(sm + a_off + bo + 16) = rAh[1];
            *(uint4*)(sm + a_off + bo + OFF_ALO) = rAl[0];
            *(uint4*)(sm + a_off + bo + OFF_ALO + 16) = rAl[1];
        } else if constexpr (AM == 1) {
#pragma unroll
            for (int j = 0; j < 16; j++) {
                float v = rA[j];
                __nv_bfloat16 h = __float2bfloat16(v);
                __nv_bfloat16 l = __float2bfloat16(v - __bfloat162float(h));
                uint32_t off = (mseg * 16 + j) * PITCH + krow * 2;
                *(__nv_bfloat16*)(sm + bo + off) = h;
                *(__nv_bfloat16*)(sm + bo + OFF_ALO + off) = l;
            }
        } else {
            uint32_t hp[8], lp[8];
#pragma unroll
            for (int j = 0; j < 8; j++) split2(rA[2 * j], rA[2 * j + 1], hp[j], lp[j]);
            *(uint4*)(sm + bo + a_off) = *(uint4*)hp;
            *(uint4*)(sm + bo + a_off + 16) = *(uint4*)(hp + 4);
            *(uint4*)(sm + bo + OFF_ALO + a_off) = *(uint4*)lp;
            *(uint4*)(sm + bo + OFF_ALO + a_off + 16) = *(uint4*)(lp + 4);
        }
#pragma unroll
        for (int j = 0; j < 8; j += 2) {
            uint32_t hp, lp;
            split2(rB[j], rB[j + 1], hp, lp);
            *(uint32_t*)(sm + (b_off - OFF_BHI) + OFF_BHI + bo + j * 2) = hp;
            *(uint32_t*)(sm + (b_off - OFF_BHI) + OFF_BLO + bo + j * 2) = lp;
        }
    };

    int warp_m = wid & 3, warp_n = wid >> 2;
    uint32_t a_ld = sb + (warp_m * 32 + (lane & 15)) * PITCH + (lane >> 4) * 16;
    uint32_t b_ld = sb + OFF_BHI + (warp_n * 32 + (lane & 15)) * PITCH + (lane >> 4) * 16;

    float acc[2][4][4];
#pragma unroll
    for (int i = 0; i < 2; i++)
#pragma unroll
        for (int j = 0; j < 4; j++)
#pragma unroll
            for (int e = 0; e < 4; e++) acc[i][j][e] = 0.f;

    load_gmem(0);
    store_smem(0);
    __syncthreads();

    for (int ch = 0; ch < NCH; ch++) {
        if (ch + 1 < NCH) load_gmem(ch + 1);
        uint32_t bo = (ch & 1) * STAGE;
#pragma unroll
        for (int ks = 0; ks < 2; ks++) {
            uint32_t Ah[2][4], Al[2][4], Bh[2][4], Bl[2][4];
#pragma unroll
            for (int mt = 0; mt < 2; mt++) {
                ldsm4(a_ld + bo + mt * (16 * PITCH) + ks * 32, Ah[mt]);
                ldsm4(a_ld + bo + OFF_ALO + mt * (16 * PITCH) + ks * 32, Al[mt]);
            }
#pragma unroll
            for (int gq = 0; gq < 2; gq++) {
                ldsm4(b_ld + bo + gq * (16 * PITCH) + ks * 32, Bh[gq]);
                ldsm4(b_ld + bo + (OFF_BLO - OFF_BHI) + gq * (16 * PITCH) + ks * 32, Bl[gq]);
            }
#pragma unroll
            for (int mt = 0; mt < 2; mt++)
#pragma unroll
                for (int nt = 0; nt < 4; nt++) {
                    int gq = nt >> 1, idx = nt & 1;
                    uint32_t bh0 = Bh[gq][idx], bh1 = Bh[gq][idx + 2];
                    uint32_t bl0 = Bl[gq][idx], bl1 = Bl[gq][idx + 2];
                    mma16816(acc[mt][nt], Ah[mt], bh0, bh1);
                    mma16816(acc[mt][nt], Ah[mt], bl0, bl1);
                    mma16816(acc[mt][nt], Al[mt], bh0, bh1);
                }
        }
        if (ch + 1 < NCH) {
            store_smem((ch + 1) & 1);
            __syncthreads();
        }
    }

#pragma unroll
    for (int mt = 0; mt < 2; mt++) {
#pragma unroll
        for (int half = 0; half < 2; half++) {
            int co = m0 + warp_m * 32 + mt * 16 + (lane >> 2) + half * 8;
            float bv = bias ? bias[co] : 0.f;
#pragma unroll
            for (int nt = 0; nt < 4; nt++) {
#pragma unroll
                for (int e = 0; e < 2; e++) {
                    int p = n0 + warp_n * 32 + nt * 8 + (lane & 3) * 2 + e;
                    if (p >= Nn) continue;
                    float v = acc[mt][nt][half * 2 + e] * scale + bv;
                    if (resid) v += resid[(size_t)co * ldo + p];
                    if (TRANS) outp[(size_t)p * ldo + co] = v;
                    else outp[(size_t)co * ldo + p] = v;
                }
            }
        }
    }
}

// ============================================================
// Softmax
// ============================================================
__global__ __launch_bounds__(256)
void k_softmax() {
    float* p = g_attn + (size_t)blockIdx.x * 1024;
    int tid = threadIdx.x;
    float4 v = *(float4*)(p + tid * 4);
    float mx = fmaxf(fmaxf(v.x, v.y), fmaxf(v.z, v.w));
#pragma unroll
    for (int o = 16; o > 0; o >>= 1) mx = fmaxf(mx, __shfl_xor_sync(0xffffffffu, mx, o));
    __shared__ float smx[8], ssm[8];
    if ((tid & 31) == 0) smx[tid >> 5] = mx;
    __syncthreads();
    mx = smx[0];
#pragma unroll
    for (int i = 1; i < 8; i++) mx = fmaxf(mx, smx[i]);
    float e0 = expf(v.x - mx), e1 = expf(v.y - mx), e2 = expf(v.z - mx), e3 = expf(v.w - mx);
    float s = e0 + e1 + e2 + e3;
#pragma unroll
    for (int o = 16; o > 0; o >>= 1) s += __shfl_xor_sync(0xffffffffu, s, o);
    if ((tid & 31) == 0) ssm[tid >> 5] = s;
    __syncthreads();
    s = ssm[0] + ssm[1] + ssm[2] + ssm[3] + ssm[4] + ssm[5] + ssm[6] + ssm[7];
    float inv = 1.f / s;
    *(float4*)(p + tid * 4) = make_float4(e0 * inv, e1 * inv, e2 * inv, e3 * inv);
}

// ============================================================
// Grid sample (packs output), BN fold, c3 (unpacks input)
// ============================================================
__device__ __forceinline__ int map_idx(int o, int size, bool* valid) {
    float vv = -49.f + 2.f * (float)o;
    float gg = (vv + 51.2f) / 102.4f * 2.f - 1.f;
    float f = ((gg + 1.f) * (float)size - 1.f) * 0.5f;
    int ii = (int)rintf(f);
    *valid = (ii >= 0) && (ii < size);
    return min(max(ii, 0), size - 1);
}

__global__ void k_gridsample() {
    int idx = blockIdx.x * 256 + threadIdx.x;
    if (idx >= 512 * 2500) return;
    int c = idx / 2500, p = idx - c * 2500;
    int oy = p / 50, ox = p - oy * 50;
    bool vy, vx;
    int iy = map_idx(oy, 32, &vy);
    int ix = map_idx(ox, 32, &vx);
    float v = (vy && vx) ? g_x[(size_t)c * 1024 + iy * 32 + ix] : 0.f;
    g_xs[idx] = packbf(v);
}

__global__ void k_bnprep(const float* g1, const float* b1, const float* m1, const float* v1,
                         const float* g2, const float* b2, const float* m2, const float* v2) {
    int c = blockIdx.x * 256 + threadIdx.x;
    if (c >= 512) return;
    float s1 = g1[c] / sqrtf(v1[c] + 1e-5f);
    g_bn[c] = s1;
    g_bn[512 + c] = b1[c] - m1[c] * s1;
    float s2 = g2[c] / sqrtf(v2[c] + 1e-5f);
    g_bn[1024 + c] = s2;
    g_bn[1536 + c] = b2[c] - m2[c] * s2;
}

__global__ void k_c3(const float* __restrict__ w, const float* __restrict__ b,
                     float* __restrict__ out) {
    int idx = blockIdx.x * 256 + threadIdx.x;
    if (idx >= 60000) return;
    int cls = idx / 10000, p = idx - cls * 10000;
    const float* wr = w + cls * 512;
    float s = b[cls];
#pragma unroll 4
    for (int c = 0; c < 512; c++) s += unpackbf(g_y1[(size_t)c * 10000 + p]) * wr[c];
    out[idx] = 1.f / (1.f + expf(-s));
}

// ============================================================
// Host orchestration
// ============================================================
extern "C" void kernel_launch(void* const* d_in, const int* in_sizes, int n_in,
                              void* d_out, int out_size) {
    const float* x       = (const float*)d_in[0];
    const float* qkv_w   = (const float*)d_in[1];
    const float* proj_w  = (const float*)d_in[2];
    const float* proj_b  = (const float*)d_in[3];
    const float* head_w  = (const float*)d_in[4];
    const float* head_b  = (const float*)d_in[5];
    const float* body_w  = (const float*)d_in[6];
    const float* body_b  = (const float*)d_in[7];
    const float* btail_w = (const float*)d_in[8];
    const float* btail_b = (const float*)d_in[9];
    const float* up_w    = (const float*)d_in[10];
    const float* up_b    = (const float*)d_in[11];
    const float* tail_w  = (const float*)d_in[12];
    const float* tail_b  = (const float*)d_in[13];
    const float* c1_w    = (const float*)d_in[14];
    const float* bn1_g   = (const float*)d_in[15];
    const float* bn1_b   = (const float*)d_in[16];
    const float* bn1_m   = (const float*)d_in[17];
    const float* bn1_v   = (const float*)d_in[18];
    const float* c2_w    = (const float*)d_in[19];
    const float* bn2_g   = (const float*)d_in[20];
    const float* bn2_b   = (const float*)d_in[21];
    const float* bn2_m   = (const float*)d_in[22];
    const float* bn2_v   = (const float*)d_in[23];
    const float* c3_w    = (const float*)d_in[24];
    const float* c3_b    = (const float*)d_in[25];
    float* out = (float*)d_out;

    float *p_x, *p_t, *p_qkv, *p_attn, *p_res, *p_bn;
    uint32_t *p_xs, *p_h, *p_r, *p_tmp, *p_u, *p_y1, *p_y2;
    __nv_bfloat16 *p_whi, *p_wlo, *p_aqh, *p_aql, *p_aph, *p_apl;
    cudaGetSymbolAddress((void**)&p_x, g_x);
    cudaGetSymbolAddress((void**)&p_t, g_t);
    cudaGetSymbolAddress((void**)&p_qkv, g_qkv);
    cudaGetSymbolAddress((void**)&p_attn, g_attn);
    cudaGetSymbolAddress((void**)&p_res, g_res);
    cudaGetSymbolAddress((void**)&p_xs, g_xs);
    cudaGetSymbolAddress((void**)&p_h, g_h);
    cudaGetSymbolAddress((void**)&p_r, g_r);
    cudaGetSymbolAddress((void**)&p_tmp, g_tmp);
    cudaGetSymbolAddress((void**)&p_u, g_u);
    cudaGetSymbolAddress((void**)&p_y1, g_y1);
    cudaGetSymbolAddress((void**)&p_y2, g_y2);
    cudaGetSymbolAddress((void**)&p_bn, g_bn);
    cudaGetSymbolAddress((void**)&p_whi, g_whi);
    cudaGetSymbolAddress((void**)&p_wlo, g_wlo);
    cudaGetSymbolAddress((void**)&p_aqh, g_aqh);
    cudaGetSymbolAddress((void**)&p_aql, g_aql);
    cudaGetSymbolAddress((void**)&p_aph, g_aph);
    cudaGetSymbolAddress((void**)&p_apl, g_apl);

    cudaFuncSetAttribute(k_convtc, cudaFuncAttributeMaxDynamicSharedMemorySize, SMEM_DYN);
    cudaFuncSetAttribute(k_agemm<0, 0>, cudaFuncAttributeMaxDynamicSharedMemorySize, SMEM_DYN);
    cudaFuncSetAttribute(k_agemm<0, 1>, cudaFuncAttributeMaxDynamicSharedMemorySize, SMEM_DYN);
    cudaFuncSetAttribute(k_agemm<1, 0>, cudaFuncAttributeMaxDynamicSharedMemorySize, SMEM_DYN);
    cudaFuncSetAttribute(k_agemm<2, 1>, cudaFuncAttributeMaxDynamicSharedMemorySize, SMEM_DYN);

    cudaMemcpyAsync(p_x, x, (size_t)512 * 1024 * sizeof(float),
                    cudaMemcpyDeviceToDevice, 0);

    // ---- weight prep ----
    {
        struct { const float* s; int off; int n; } regs[7] = {
            {head_w,  W_HEAD,  2359296},
            {body_w,  W_BODY,  37748736},
            {btail_w, W_BTAIL, 2359296},
            {up_w,    W_UP,    9437184},
            {tail_w,  W_TAIL,  2359296},
            {c1_w,    W_C1,    2359296},
            {c2_w,    W_C2,    2359296},
        };
        for (int i = 0; i < 7; i++)
            k_wprep<<<(regs[i].n + 255) / 256, 256>>>(regs[i].s, p_whi + regs[i].off,
                                                      p_wlo + regs[i].off, regs[i].n);
        k_wtq<<<(8 * 1536 * 512 + 255) / 256, 256>>>(qkv_w, p_aqh, p_aql);
        k_wtp<<<(8 * 512 * 512 + 255) / 256, 256>>>(proj_w, p_aph, p_apl);
    }

    const float scale = 0.044194173824159216f;  // 512^-0.5

    // ---- 8 self-attention blocks ----
    for (int i = 0; i < 8; i++) {
        k_agemm<0, 0><<<dim3(16, 8, 1), 256, SMEM_DYN>>>(
            p_aqh + (size_t)i * 1536 * 512, p_aql + (size_t)i * 1536 * 512,
            nullptr, p_x, p_qkv, nullptr, nullptr,
            0, 0, 0, 512, 512, 1024, 1024, 1024, 1.f);
        k_agemm<0, 1><<<dim3(16, 4, 1), 256, SMEM_DYN>>>(
            p_aqh + (size_t)i * 1536 * 512 + (size_t)1024 * 512,
            p_aql + (size_t)i * 1536 * 512 + (size_t)1024 * 512,
            nullptr, p_x, p_t, nullptr, nullptr,
            0, 0, 0, 512, 512, 1024, 512, 1024, 1.f);
        k_agemm<1, 0><<<dim3(16, 8, 8), 256, SMEM_DYN>>>(
            nullptr, nullptr, p_qkv, p_qkv + (size_t)512 * 1024, p_attn,
            nullptr, nullptr,
            64 * 1024, 64 * 1024, 1l << 20, 64, 1024, 1024, 1024, 1024, scale);
        k_softmax<<<8192, 256>>>();
        k_agemm<2, 1><<<dim3(1, 8, 8), 256, SMEM_DYN>>>(
            nullptr, nullptr, p_attn, p_t, p_res, nullptr, nullptr,
            1l << 20, 64, 64 * 1024, 1024, 1024, 512, 1024, 64, 1.f);
        k_agemm<0, 0><<<dim3(16, 4, 1), 256, SMEM_DYN>>>(
            p_aph + (size_t)i * 512 * 512, p_apl + (size_t)i * 512 * 512,
            nullptr, p_res, p_x, proj_b + (size_t)i * 512, p_x,
            0, 0, 0, 512, 512, 1024, 1024, 1024, 1.f);
    }

    // ---- grid transform + BN fold ----
    k_gridsample<<<(512 * 2500 + 255) / 256, 256>>>();
    k_bnprep<<<2, 256>>>(bn1_g, bn1_b, bn1_m, bn1_v, bn2_g, bn2_b, bn2_m, bn2_v);

    // ---- EDSR upsampler ----
    dim3 g50(40, 4);
    k_convtc<<<g50, 256, SMEM_DYN>>>(p_xs, p_whi + W_HEAD, p_wlo + W_HEAD, head_b,
                                     nullptr, nullptr, nullptr, p_h, 50, 50, 0, 0);
    cudaMemcpyAsync(p_r, p_h, (size_t)512 * 2500 * sizeof(uint32_t),
                    cudaMemcpyDeviceToDevice, 0);
    for (int i = 0; i < 8; i++) {
        int o0 = W_BODY + (2 * i) * 2359296;
        int o1 = W_BODY + (2 * i + 1) * 2359296;
        k_convtc<<<g50, 256, SMEM_DYN>>>(p_r, p_whi + o0, p_wlo + o0,
                                         body_b + (size_t)(2 * i) * 512,
                                         nullptr, nullptr, nullptr, p_tmp, 50, 50, 1, 0);
        k_convtc<<<g50, 256, SMEM_DYN>>>(p_tmp, p_whi + o1, p_wlo + o1,
                                         body_b + (size_t)(2 * i + 1) * 512,
                                         nullptr, nullptr, p_r, p_r, 50, 50, 0, 0);
    }
    k_convtc<<<g50, 256, SMEM_DYN>>>(p_r, p_whi + W_BTAIL, p_wlo + W_BTAIL, btail_b,
                                     nullptr, nullptr, p_h, p_tmp, 50, 50, 0, 0);
    k_convtc<<<dim3(40, 16), 256, SMEM_DYN>>>(p_tmp, p_whi + W_UP, p_wlo + W_UP, up_b,
                                              nullptr, nullptr, nullptr, p_u, 50, 50, 0, 1);
    dim3 g100(157, 4);
    k_convtc<<<g100, 256, SMEM_DYN>>>(p_u, p_whi + W_TAIL, p_wlo + W_TAIL, tail_b,
                                      nullptr, nullptr, nullptr, p_y1, 100, 100, 0, 0);

    // ---- classifier ----
    k_convtc<<<g100, 256, SMEM_DYN>>>(p_y1, p_whi + W_C1, p_wlo + W_C1, nullptr,
                                      p_bn, p_bn + 512, nullptr, p_y2, 100, 100, 1, 0);
    k_convtc<<<g100, 256, SMEM_DYN>>>(p_y2, p_whi + W_C2, p_wlo + W_C2, nullptr,
                                      p_bn + 1024, p_bn + 1536, nullptr, p_y1, 100, 100, 1, 0);
    k_c3<<<(60000 + 255) / 256, 256>>>(c3_w, c3_b, out);
}

// round 11
// speedup vs baseline: 3.5833x; 2.0509x over previous
#include <cuda_runtime.h>
#include <cuda_bf16.h>
#include <math.h>
#include <stdint.h>

// ============================================================
// Static device scratch
// ============================================================
__device__ float g_x[512 * 1024];        // attention state, C-major
__device__ float g_t[1024 * 512];        // V token-major
__device__ float g_qkv[1024 * 1024];     // Q,K feature-major
__device__ float g_attn[8 * 1024 * 1024];
__device__ float g_res[512 * 1024];      // attn out feature-major
// packed bf16x2 activation planes (hi lo16, lo hi16)
__device__ uint32_t g_xs[512 * 2500];
__device__ uint32_t g_h[512 * 2500];
__device__ uint32_t g_r[512 * 2500];
__device__ uint32_t g_tmp[512 * 2500];
__device__ uint32_t g_u[512 * 10000];
__device__ uint32_t g_y1[512 * 10000];
__device__ uint32_t g_y2[512 * 10000];
__device__ float g_bn[2048];

// Winograd-transformed conv weights, presplit hi/lo.
// Layout per layer: [16 points][Cout][Cin=512].
// Std layer = 16*512*512 = 4194304 elems. up = 16*2048*512.
#define UL 4194304
#define U_HEAD  ((size_t)0)
#define U_BODY(i) ((size_t)(1 + (i)) * UL)     // i in 0..15
#define U_BTAIL ((size_t)17 * UL)
#define U_TAIL  ((size_t)18 * UL)
#define U_C1    ((size_t)19 * UL)
#define U_C2    ((size_t)20 * UL)
#define U_UP    ((size_t)21 * UL)
#define U_TOTAL ((size_t)21 * UL + 16777216)   // 104857600
__device__ __nv_bfloat16 g_uhi[U_TOTAL];
__device__ __nv_bfloat16 g_ulo[U_TOTAL];

// Winograd activation buffer V[16][512][NTpad<=2560], packed bf16x2
__device__ uint32_t g_v[16 * 512 * 2560];
// GEMM output M[16][Cout][NTpad] fp32 (max 16*512*2560 = 16*2048*640)
__device__ float g_m[16 * 512 * 2560];

// attention weights presplit + transposed
__device__ __nv_bfloat16 g_aqh[8 * 1536 * 512];
__device__ __nv_bfloat16 g_aql[8 * 1536 * 512];
__device__ __nv_bfloat16 g_aph[8 * 512 * 512];
__device__ __nv_bfloat16 g_apl[8 * 512 * 512];

// ============================================================
// Helpers
// ============================================================
__device__ __forceinline__ uint32_t smem_u32(const void* p) {
    uint32_t a;
    asm("{ .reg .u64 t; cvta.to.shared.u64 t, %1; cvt.u32.u64 %0, t; }"
        : "=r"(a) : "l"(p));
    return a;
}

__device__ __forceinline__ void cpasync16(uint32_t dst, const void* src) {
    asm volatile("cp.async.ca.shared.global [%0], [%1], 16;" :: "r"(dst), "l"(src));
}
#define CP_COMMIT asm volatile("cp.async.commit_group;" ::: "memory")
#define CP_WAIT0  asm volatile("cp.async.wait_group 0;" ::: "memory")

__device__ __forceinline__ void ldsm4(uint32_t addr, uint32_t* r) {
    asm volatile("ldmatrix.sync.aligned.m8n8.x4.shared.b16 {%0,%1,%2,%3}, [%4];"
                 : "=r"(r[0]), "=r"(r[1]), "=r"(r[2]), "=r"(r[3]) : "r"(addr));
}

__device__ __forceinline__ void mma16816(float* d, const uint32_t* a,
                                         uint32_t b0, uint32_t b1) {
    asm volatile(
        "mma.sync.aligned.m16n8k16.row.col.f32.bf16.bf16.f32 "
        "{%0,%1,%2,%3}, {%4,%5,%6,%7}, {%8,%9}, {%0,%1,%2,%3};"
        : "+f"(d[0]), "+f"(d[1]), "+f"(d[2]), "+f"(d[3])
        : "r"(a[0]), "r"(a[1]), "r"(a[2]), "r"(a[3]), "r"(b0), "r"(b1));
}

__device__ __forceinline__ void split2(float v0, float v1, uint32_t& hp, uint32_t& lp) {
    __nv_bfloat16 h0 = __float2bfloat16(v0), h1 = __float2bfloat16(v1);
    __nv_bfloat16 l0 = __float2bfloat16(v0 - __bfloat162float(h0));
    __nv_bfloat16 l1 = __float2bfloat16(v1 - __bfloat162float(h1));
    hp = (uint32_t)__bfloat16_as_ushort(h0) | ((uint32_t)__bfloat16_as_ushort(h1) << 16);
    lp = (uint32_t)__bfloat16_as_ushort(l0) | ((uint32_t)__bfloat16_as_ushort(l1) << 16);
}

__device__ __forceinline__ uint32_t packbf(float v) {
    __nv_bfloat16 h = __float2bfloat16(v);
    __nv_bfloat16 l = __float2bfloat16(v - __bfloat162float(h));
    return (uint32_t)__bfloat16_as_ushort(h) | ((uint32_t)__bfloat16_as_ushort(l) << 16);
}

__device__ __forceinline__ float unpackbf(uint32_t p) {
    return __bfloat162float(__ushort_as_bfloat16((unsigned short)(p & 0xffff))) +
           __bfloat162float(__ushort_as_bfloat16((unsigned short)(p >> 16)));
}

// ============================================================
// Weight prep: Winograd transform + split. One thread per (co,ci).
// U = G g G^T, G = [[1,0,0],[.5,.5,.5],[.5,-.5,.5],[0,0,1]]
// ============================================================
__global__ void k_wwino(const float* __restrict__ w, __nv_bfloat16* __restrict__ uhi,
                        __nv_bfloat16* __restrict__ ulo, int Cout, int Cin) {
    int idx = blockIdx.x * 256 + threadIdx.x;
    if (idx >= Cout * Cin) return;
    int co = idx / Cin, ci = idx - co * Cin;
    const float* gp = w + (size_t)idx * 9;
    float g0 = gp[0], g1 = gp[1], g2 = gp[2];
    float g3 = gp[3], g4 = gp[4], g5 = gp[5];
    float g6 = gp[6], g7 = gp[7], g8 = gp[8];
    // t = G g  (4x3)
    float t[4][3];
    t[0][0] = g0; t[0][1] = g1; t[0][2] = g2;
    t[1][0] = 0.5f * (g0 + g3 + g6); t[1][1] = 0.5f * (g1 + g4 + g7); t[1][2] = 0.5f * (g2 + g5 + g8);
    t[2][0] = 0.5f * (g0 - g3 + g6); t[2][1] = 0.5f * (g1 - g4 + g7); t[2][2] = 0.5f * (g2 - g5 + g8);
    t[3][0] = g6; t[3][1] = g7; t[3][2] = g8;
    // U = t G^T (4x4)
#pragma unroll
    for (int i = 0; i < 4; i++) {
        float a0 = t[i][0], a1 = t[i][1], a2 = t[i][2];
        float u[4];
        u[0] = a0;
        u[1] = 0.5f * (a0 + a1 + a2);
        u[2] = 0.5f * (a0 - a1 + a2);
        u[3] = a2;
#pragma unroll
        for (int j = 0; j < 4; j++) {
            int p = i * 4 + j;
            size_t o = (size_t)p * Cout * Cin + (size_t)co * Cin + ci;
            float v = u[j];
            __nv_bfloat16 h = __float2bfloat16(v);
            uhi[o] = h;
            ulo[o] = __float2bfloat16(v - __bfloat162float(h));
        }
    }
}

// qkv_w (8,512,1536) -> transposed (8,1536,512) split
__global__ void k_wtq(const float* __restrict__ src, __nv_bfloat16* __restrict__ hi,
                      __nv_bfloat16* __restrict__ lo) {
    int idx = blockIdx.x * 256 + threadIdx.x;
    if (idx >= 8 * 1536 * 512) return;
    int blk = idx / (1536 * 512), r = idx - blk * (1536 * 512);
    int f = r >> 9, c = r & 511;
    float v = src[(size_t)blk * 512 * 1536 + c * 1536 + f];
    __nv_bfloat16 h = __float2bfloat16(v);
    hi[idx] = h;
    lo[idx] = __float2bfloat16(v - __bfloat162float(h));
}

__global__ void k_wtp(const float* __restrict__ src, __nv_bfloat16* __restrict__ hi,
                      __nv_bfloat16* __restrict__ lo) {
    int idx = blockIdx.x * 256 + threadIdx.x;
    if (idx >= 8 * 512 * 512) return;
    int blk = idx / (512 * 512), r = idx - blk * (512 * 512);
    int f = r >> 9, c = r & 511;
    float v = src[(size_t)blk * 512 * 512 + c * 512 + f];
    __nv_bfloat16 h = __float2bfloat16(v);
    hi[idx] = h;
    lo[idx] = __float2bfloat16(v - __bfloat162float(h));
}

// ============================================================
// Winograd input transform: packed plane [512][H*H] -> V[16][512][NTpad]
// B^T d B with B^T = [[1,0,-1,0],[0,1,1,0],[0,-1,1,0],[0,1,0,-1]]
// ============================================================
__global__ void k_wino_in(const uint32_t* __restrict__ in, uint32_t* __restrict__ V,
                          int H, int T, int NTpad) {
    int idx = blockIdx.x * 256 + threadIdx.x;
    if (idx >= 512 * NTpad) return;
    int c = idx / NTpad, t = idx - c * NTpad;
    size_t pstride = (size_t)512 * NTpad;
    if (t >= T * T) {
#pragma unroll
        for (int p = 0; p < 16; p++) V[(size_t)p * pstride + idx] = 0;
        return;
    }
    int ty = t / T, tx = t - ty * T;
    int r0 = 2 * ty - 1, c0 = 2 * tx - 1;
    const uint32_t* ip = in + (size_t)c * H * H;
    float d[4][4];
#pragma unroll
    for (int i = 0; i < 4; i++) {
        int rr = r0 + i;
        bool rv = (unsigned)rr < (unsigned)H;
#pragma unroll
        for (int j = 0; j < 4; j++) {
            int cc = c0 + j;
            d[i][j] = (rv && (unsigned)cc < (unsigned)H) ? unpackbf(ip[rr * H + cc]) : 0.f;
        }
    }
    float e[4][4];
#pragma unroll
    for (int j = 0; j < 4; j++) {
        e[0][j] = d[0][j] - d[2][j];
        e[1][j] = d[1][j] + d[2][j];
        e[2][j] = d[2][j] - d[1][j];
        e[3][j] = d[1][j] - d[3][j];
    }
#pragma unroll
    for (int i = 0; i < 4; i++) {
        float f0 = e[i][0] - e[i][2];
        float f1 = e[i][1] + e[i][2];
        float f2 = e[i][2] - e[i][1];
        float f3 = e[i][1] - e[i][3];
        V[(size_t)(i * 4 + 0) * pstride + idx] = packbf(f0);
        V[(size_t)(i * 4 + 1) * pstride + idx] = packbf(f1);
        V[(size_t)(i * 4 + 2) * pstride + idx] = packbf(f2);
        V[(size_t)(i * 4 + 3) * pstride + idx] = packbf(f3);
    }
}

// ============================================================
// Shared smem layout for GEMMs
// ============================================================
#define PITCH 80
#define OFF_ALO (128 * PITCH)
#define OFF_BHI (2 * 128 * PITCH)
#define OFF_BLO (OFF_BHI + 64 * PITCH)
#define STAGE   (OFF_BLO + 64 * PITCH)   // 30720
#define SMEM_DYN (2 * STAGE)             // 61440

// ============================================================
// Winograd batched GEMM: out[z][M][N] = U[z][M][512] @ V[z][512][N]
// z = 16 Winograd points. A presplit bf16 (cp.async), B packed bf16x2 u32.
// Tile M=128 x N=64, K=512 (16 chunks of 32), double-buffered.
// ============================================================
__global__ __launch_bounds__(256, 2)
void k_wgemm(const __nv_bfloat16* __restrict__ Ahi, const __nv_bfloat16* __restrict__ Alo,
             const uint32_t* __restrict__ Bp, float* __restrict__ outg,
             long aoz, long boz, long coz, int ldb) {
    extern __shared__ char sm[];
    int tid = threadIdx.x, wid = tid >> 5, lane = tid & 31;
    int n0 = blockIdx.x * 64, m0 = blockIdx.y * 128, z = blockIdx.z;
    uint32_t sb = smem_u32(sm);

    int arow = tid >> 1, aseg = tid & 1;
    const __nv_bfloat16* whp = Ahi + (size_t)z * aoz + (size_t)(m0 + arow) * 512 + aseg * 16;
    const __nv_bfloat16* wlp = Alo + (size_t)z * aoz + (size_t)(m0 + arow) * 512 + aseg * 16;
    uint32_t a_off = arow * PITCH + aseg * 32;

    int bpix = tid & 63, bkg = tid >> 6;
    const uint32_t* bbase = Bp + (size_t)z * boz + n0 + bpix;
    uint32_t b_off = OFF_BHI + bpix * PITCH + bkg * 16;

    uint32_t rBp[8];

    auto a_issue = [&](int ch, int buf) {
        int kk = ch << 5;
        uint32_t d0 = sb + a_off + buf * STAGE;
        cpasync16(d0, whp + kk);
        cpasync16(d0 + 16, whp + kk + 8);
        cpasync16(d0 + OFF_ALO, wlp + kk);
        cpasync16(d0 + OFF_ALO + 16, wlp + kk + 8);
        CP_COMMIT;
    };
    auto b_load = [&](int ch) {
        int kk = ch << 5;
#pragma unroll
        for (int j = 0; j < 8; j++)
            rBp[j] = bbase[(size_t)(kk + bkg * 8 + j) * ldb];
    };
    auto b_store = [&](int buf) {
        uint32_t bo = buf * STAGE;
#pragma unroll
        for (int j = 0; j < 8; j += 2) {
            uint32_t hp = __byte_perm(rBp[j], rBp[j + 1], 0x5410);
            uint32_t lp = __byte_perm(rBp[j], rBp[j + 1], 0x7632);
            *(uint32_t*)(sm + (b_off - OFF_BHI) + OFF_BHI + bo + j * 2) = hp;
            *(uint32_t*)(sm + (b_off - OFF_BHI) + OFF_BLO + bo + j * 2) = lp;
        }
    };

    int warp_m = wid & 3, warp_n = wid >> 2;
    uint32_t a_ld = sb + (warp_m * 32 + (lane & 15)) * PITCH + (lane >> 4) * 16;
    uint32_t b_ld = sb + OFF_BHI + (warp_n * 32 + (lane & 15)) * PITCH + (lane >> 4) * 16;

    float acc[2][4][4];
#pragma unroll
    for (int i = 0; i < 2; i++)
#pragma unroll
        for (int j = 0; j < 4; j++)
#pragma unroll
            for (int e = 0; e < 4; e++) acc[i][j][e] = 0.f;

    a_issue(0, 0);
    b_load(0);
    b_store(0);
    CP_WAIT0;
    __syncthreads();

    for (int ch = 0; ch < 16; ch++) {
        if (ch < 15) {
            a_issue(ch + 1, (ch + 1) & 1);
            b_load(ch + 1);
        }
        uint32_t bo = (ch & 1) * STAGE;
#pragma unroll
        for (int ks = 0; ks < 2; ks++) {
            uint32_t Ah[2][4], Al[2][4], Bh[2][4], Bl[2][4];
#pragma unroll
            for (int mt = 0; mt < 2; mt++) {
                ldsm4(a_ld + bo + mt * (16 * PITCH) + ks * 32, Ah[mt]);
                ldsm4(a_ld + bo + OFF_ALO + mt * (16 * PITCH) + ks * 32, Al[mt]);
            }
#pragma unroll
            for (int gq = 0; gq < 2; gq++) {
                ldsm4(b_ld + bo + gq * (16 * PITCH) + ks * 32, Bh[gq]);
                ldsm4(b_ld + bo + (OFF_BLO - OFF_BHI) + gq * (16 * PITCH) + ks * 32, Bl[gq]);
            }
#pragma unroll
            for (int mt = 0; mt < 2; mt++)
#pragma unroll
                for (int nt = 0; nt < 4; nt++) {
                    int gq = nt >> 1, idx = nt & 1;
                    uint32_t bh0 = Bh[gq][idx], bh1 = Bh[gq][idx + 2];
                    uint32_t bl0 = Bl[gq][idx], bl1 = Bl[gq][idx + 2];
                    mma16816(acc[mt][nt], Ah[mt], bh0, bh1);
                    mma16816(acc[mt][nt], Ah[mt], bl0, bl1);
                    mma16816(acc[mt][nt], Al[mt], bh0, bh1);
                }
        }
        if (ch < 15) {
            b_store((ch + 1) & 1);
            CP_WAIT0;
            __syncthreads();
        }
    }

    float* op = outg + (size_t)z * coz;
#pragma unroll
    for (int mt = 0; mt < 2; mt++) {
#pragma unroll
        for (int half = 0; half < 2; half++) {
            int co = m0 + warp_m * 32 + mt * 16 + (lane >> 2) + half * 8;
#pragma unroll
            for (int nt = 0; nt < 4; nt++) {
#pragma unroll
                for (int e = 0; e < 2; e++) {
                    int p = n0 + warp_n * 32 + nt * 8 + (lane & 3) * 2 + e;
                    op[(size_t)co * ldb + p] = acc[mt][nt][half * 2 + e];
                }
            }
        }
    }
}

// ============================================================
// Winograd output transform: M[16][Cout][NTpad] -> plane, fused epilogue.
// Y = A^T M A, A^T = [[1,1,1,0],[0,1,-1,-1]]
// ============================================================
__global__ void k_wino_out(const float* __restrict__ Mb, uint32_t* __restrict__ out,
                           const float* __restrict__ bias,
                           const float* __restrict__ bnsc, const float* __restrict__ bnsh,
                           const uint32_t* __restrict__ resid,
                           int Cout, int T, int NTpad, int relu, int ps) {
    int idx = blockIdx.x * 256 + threadIdx.x;
    if (idx >= Cout * T * T) return;
    int co = idx / (T * T), t = idx - co * (T * T);
    int ty = t / T, tx = t - ty * T;
    int H = 2 * T, P = H * H;
    size_t pstride = (size_t)Cout * NTpad;
    const float* mp = Mb + (size_t)co * NTpad + t;
    float m[4][4];
#pragma unroll
    for (int i = 0; i < 4; i++)
#pragma unroll
        for (int j = 0; j < 4; j++)
            m[i][j] = mp[(size_t)(i * 4 + j) * pstride];
    float s0[4], s1[4];
#pragma unroll
    for (int j = 0; j < 4; j++) {
        s0[j] = m[0][j] + m[1][j] + m[2][j];
        s1[j] = m[1][j] - m[2][j] - m[3][j];
    }
    float y[2][2];
    y[0][0] = s0[0] + s0[1] + s0[2];
    y[0][1] = s0[1] - s0[2] - s0[3];
    y[1][0] = s1[0] + s1[1] + s1[2];
    y[1][1] = s1[1] - s1[2] - s1[3];

    float bv = bias ? bias[co] : 0.f;
    float sc = bnsc ? bnsc[co] : 1.f;
    float sh = bnsh ? bnsh[co] : 0.f;
#pragma unroll
    for (int i = 0; i < 2; i++) {
#pragma unroll
        for (int j = 0; j < 2; j++) {
            int yy = 2 * ty + i, xx = 2 * tx + j;
            int pix = yy * H + xx;
            float v = y[i][j] + bv;
            if (bnsc) v = v * sc + sh;
            if (resid) v += unpackbf(resid[(size_t)co * P + pix]);
            if (relu) v = fmaxf(v, 0.f);
            uint32_t pk = packbf(v);
            if (ps) {
                int c = co >> 2, ry = (co >> 1) & 1, rx = co & 1;
                out[(size_t)c * (4 * P) + (size_t)(2 * yy + ry) * (2 * H) + 2 * xx + rx] = pk;
            } else {
                out[(size_t)co * P + pix] = pk;
            }
        }
    }
}

// ============================================================
// Attention tensor GEMM (unchanged, proven)
// ============================================================
template <int AM, int TRANS>
__global__ __launch_bounds__(256, 2)
void k_agemm(const __nv_bfloat16* __restrict__ Ahi, const __nv_bfloat16* __restrict__ Alo,
             const float* __restrict__ Af, const float* __restrict__ Bfg,
             float* __restrict__ outg, const float* __restrict__ bias,
             const float* __restrict__ resid,
             long aoz, long boz, long coz,
             int K, int lda, int ldb, int ldo, int Nn, float scale) {
    extern __shared__ char sm[];
    int tid = threadIdx.x, wid = tid >> 5, lane = tid & 31;
    int n0 = blockIdx.x * 64, m0 = blockIdx.y * 128, z = blockIdx.z;
    uint32_t sb = smem_u32(sm);
    int NCH = K >> 5;

    const float* Bf = Bfg + (size_t)z * boz;
    float* outp = outg + (size_t)z * coz;

    int arow = tid >> 1, aseg = tid & 1;
    int krow = tid >> 3, mseg = tid & 7;
    const __nv_bfloat16 *whp = nullptr, *wlp = nullptr;
    const float* afp = nullptr;
    if constexpr (AM == 0) {
        whp = Ahi + (size_t)z * aoz + (size_t)(m0 + arow) * lda + aseg * 16;
        wlp = Alo + (size_t)z * aoz + (size_t)(m0 + arow) * lda + aseg * 16;
    } else if constexpr (AM == 1) {
        afp = Af + (size_t)z * aoz + (size_t)krow * lda + m0 + mseg * 16;
    } else {
        afp = Af + (size_t)z * aoz + (size_t)(m0 + arow) * lda + aseg * 16;
    }
    uint32_t a_off = arow * PITCH + aseg * 32;

    int bpix = tid & 63, bkg = tid >> 6;
    uint32_t b_off = OFF_BHI + bpix * PITCH + bkg * 16;

    uint4 rAh[2], rAl[2];
    float rA[16];
    float rB[8];

    auto load_gmem = [&](int ch) {
        int kk = ch << 5;
        if constexpr (AM == 0) {
            rAh[0] = *(const uint4*)(whp + kk);
            rAh[1] = *(const uint4*)(whp + kk + 8);
            rAl[0] = *(const uint4*)(wlp + kk);
            rAl[1] = *(const uint4*)(wlp + kk + 8);
        } else if constexpr (AM == 1) {
            const float* p = afp + (size_t)kk * lda;
            *(float4*)(rA + 0) = *(const float4*)(p + 0);
            *(float4*)(rA + 4) = *(const float4*)(p + 4);
            *(float4*)(rA + 8) = *(const float4*)(p + 8);
            *(float4*)(rA + 12) = *(const float4*)(p + 12);
        } else {
            const float* p = afp + kk;
            *(float4*)(rA + 0) = *(const float4*)(p + 0);
            *(float4*)(rA + 4) = *(const float4*)(p + 4);
            *(float4*)(rA + 8) = *(const float4*)(p + 8);
            *(float4*)(rA + 12) = *(const float4*)(p + 12);
        }
#pragma unroll
        for (int j = 0; j < 8; j++)
            rB[j] = Bf[(size_t)(kk + bkg * 8 + j) * ldb + n0 + bpix];
    };

    auto store_smem = [&](int buf) {
        uint32_t bo = buf * STAGE;
        if constexpr (AM == 0) {
            *(uint4*)(sm + a_off + bo) = rAh[0];
            *(uint4*)(sm + a_off + bo + 16) = rAh[1];
            *(uint4*)(sm + a_off + bo + OFF_ALO) = rAl[0];
            *(uint4*)(sm + a_off + bo + OFF_ALO + 16) = rAl[1];
        } else if constexpr (AM == 1) {
#pragma unroll
            for (int j = 0; j < 16; j++) {
                float v = rA[j];
                __nv_bfloat16 h = __float2bfloat16(v);
                __nv_bfloat16 l = __float2bfloat16(v - __bfloat162float(h));
                uint32_t off = (mseg * 16 + j) * PITCH + krow * 2;
                *(__nv_bfloat16*)(sm + bo + off) = h;
                *(__nv_bfloat16*)(sm + bo + OFF_ALO + off) = l;
            }
        } else {
            uint32_t hp[8], lp[8];
#pragma unroll
            for (int j = 0; j < 8; j++) split2(rA[2 * j], rA[2 * j + 1], hp[j], lp[j]);
            *(uint4*)(sm + bo + a_off) = *(uint4*)hp;
            *(uint4*)(sm + bo + a_off + 16) = *(uint4*)(hp + 4);
            *(uint4*)(sm + bo + OFF_ALO + a_off) = *(uint4*)lp;
            *(uint4*)(sm + bo + OFF_ALO + a_off + 16) = *(uint4*)(lp + 4);
        }
#pragma unroll
        for (int j = 0; j < 8; j += 2) {
            uint32_t hp, lp;
            split2(rB[j], rB[j + 1], hp, lp);
            *(uint32_t*)(sm + (b_off - OFF_BHI) + OFF_BHI + bo + j * 2) = hp;
            *(uint32_t*)(sm + (b_off - OFF_BHI) + OFF_BLO + bo + j * 2) = lp;
        }
    };

    int warp_m = wid & 3, warp_n = wid >> 2;
    uint32_t a_ld = sb + (warp_m * 32 + (lane & 15)) * PITCH + (lane >> 4) * 16;
    uint32_t b_ld = sb + OFF_BHI + (warp_n * 32 + (lane & 15)) * PITCH + (lane >> 4) * 16;

    float acc[2][4][4];
#pragma unroll
    for (int i = 0; i < 2; i++)
#pragma unroll
        for (int j = 0; j < 4; j++)
#pragma unroll
            for (int e = 0; e < 4; e++) acc[i][j][e] = 0.f;

    load_gmem(0);
    store_smem(0);
    __syncthreads();

    for (int ch = 0; ch < NCH; ch++) {
        if (ch + 1 < NCH) load_gmem(ch + 1);
        uint32_t bo = (ch & 1) * STAGE;
#pragma unroll
        for (int ks = 0; ks < 2; ks++) {
            uint32_t Ah[2][4], Al[2][4], Bh[2][4], Bl[2][4];
#pragma unroll
            for (int mt = 0; mt < 2; mt++) {
                ldsm4(a_ld + bo + mt * (16 * PITCH) + ks * 32, Ah[mt]);
                ldsm4(a_ld + bo + OFF_ALO + mt * (16 * PITCH) + ks * 32, Al[mt]);
            }
#pragma unroll
            for (int gq = 0; gq < 2; gq++) {
                ldsm4(b_ld + bo + gq * (16 * PITCH) + ks * 32, Bh[gq]);
                ldsm4(b_ld + bo + (OFF_BLO - OFF_BHI) + gq * (16 * PITCH) + ks * 32, Bl[gq]);
            }
#pragma unroll
            for (int mt = 0; mt < 2; mt++)
#pragma unroll
                for (int nt = 0; nt < 4; nt++) {
                    int gq = nt >> 1, idx = nt & 1;
                    uint32_t bh0 = Bh[gq][idx], bh1 = Bh[gq][idx + 2];
                    uint32_t bl0 = Bl[gq][idx], bl1 = Bl[gq][idx + 2];
                    mma16816(acc[mt][nt], Ah[mt], bh0, bh1);
                    mma16816(acc[mt][nt], Ah[mt], bl0, bl1);
                    mma16816(acc[mt][nt], Al[mt], bh0, bh1);
                }
        }
        if (ch + 1 < NCH) {
            store_smem((ch + 1) & 1);
            __syncthreads();
        }
    }

#pragma unroll
    for (int mt = 0; mt < 2; mt++) {
#pragma unroll
        for (int half = 0; half < 2; half++) {
            int co = m0 + warp_m * 32 + mt * 16 + (lane >> 2) + half * 8;
            float bv = bias ? bias[co] : 0.f;
#pragma unroll
            for (int nt = 0; nt < 4; nt++) {
#pragma unroll
                for (int e = 0; e < 2; e++) {
                    int p = n0 + warp_n * 32 + nt * 8 + (lane & 3) * 2 + e;
                    if (p >= Nn) continue;
                    float v = acc[mt][nt][half * 2 + e] * scale + bv;
                    if (resid) v += resid[(size_t)co * ldo + p];
                    if (TRANS) outp[(size_t)p * ldo + co] = v;
                    else outp[(size_t)co * ldo + p] = v;
                }
            }
        }
    }
}

// ============================================================
// Softmax
// ============================================================
__global__ __launch_bounds__(256)
void k_softmax() {
    float* p = g_attn + (size_t)blockIdx.x * 1024;
    int tid = threadIdx.x;
    float4 v = *(float4*)(p + tid * 4);
    float mx = fmaxf(fmaxf(v.x, v.y), fmaxf(v.z, v.w));
#pragma unroll
    for (int o = 16; o > 0; o >>= 1) mx = fmaxf(mx, __shfl_xor_sync(0xffffffffu, mx, o));
    __shared__ float smx[8], ssm[8];
    if ((tid & 31) == 0) smx[tid >> 5] = mx;
    __syncthreads();
    mx = smx[0];
#pragma unroll
    for (int i = 1; i < 8; i++) mx = fmaxf(mx, smx[i]);
    float e0 = expf(v.x - mx), e1 = expf(v.y - mx), e2 = expf(v.z - mx), e3 = expf(v.w - mx);
    float s = e0 + e1 + e2 + e3;
#pragma unroll
    for (int o = 16; o > 0; o >>= 1) s += __shfl_xor_sync(0xffffffffu, s, o);
    if ((tid & 31) == 0) ssm[tid >> 5] = s;
    __syncthreads();
    s = ssm[0] + ssm[1] + ssm[2] + ssm[3] + ssm[4] + ssm[5] + ssm[6] + ssm[7];
    float inv = 1.f / s;
    *(float4*)(p + tid * 4) = make_float4(e0 * inv, e1 * inv, e2 * inv, e3 * inv);
}

// ============================================================
// Grid sample (packs), BN fold, c3 (unpacks)
// ============================================================
__device__ __forceinline__ int map_idx(int o, int size, bool* valid) {
    float vv = -49.f + 2.f * (float)o;
    float gg = (vv + 51.2f) / 102.4f * 2.f - 1.f;
    float f = ((gg + 1.f) * (float)size - 1.f) * 0.5f;
    int ii = (int)rintf(f);
    *valid = (ii >= 0) && (ii < size);
    return min(max(ii, 0), size - 1);
}

__global__ void k_gridsample() {
    int idx = blockIdx.x * 256 + threadIdx.x;
    if (idx >= 512 * 2500) return;
    int c = idx / 2500, p = idx - c * 2500;
    int oy = p / 50, ox = p - oy * 50;
    bool vy, vx;
    int iy = map_idx(oy, 32, &vy);
    int ix = map_idx(ox, 32, &vx);
    float v = (vy && vx) ? g_x[(size_t)c * 1024 + iy * 32 + ix] : 0.f;
    g_xs[idx] = packbf(v);
}

__global__ void k_bnprep(const float* g1, const float* b1, const float* m1, const float* v1,
                         const float* g2, const float* b2, const float* m2, const float* v2) {
    int c = blockIdx.x * 256 + threadIdx.x;
    if (c >= 512) return;
    float s1 = g1[c] / sqrtf(v1[c] + 1e-5f);
    g_bn[c] = s1;
    g_bn[512 + c] = b1[c] - m1[c] * s1;
    float s2 = g2[c] / sqrtf(v2[c] + 1e-5f);
    g_bn[1024 + c] = s2;
    g_bn[1536 + c] = b2[c] - m2[c] * s2;
}

__global__ void k_c3(const float* __restrict__ w, const float* __restrict__ b,
                     float* __restrict__ out) {
    int idx = blockIdx.x * 256 + threadIdx.x;
    if (idx >= 60000) return;
    int cls = idx / 10000, p = idx - cls * 10000;
    const float* wr = w + cls * 512;
    float s = b[cls];
#pragma unroll 4
    for (int c = 0; c < 512; c++) s += unpackbf(g_y1[(size_t)c * 10000 + p]) * wr[c];
    out[idx] = 1.f / (1.f + expf(-s));
}

// ============================================================
// Host orchestration
// ============================================================
extern "C" void kernel_launch(void* const* d_in, const int* in_sizes, int n_in,
                              void* d_out, int out_size) {
    const float* x       = (const float*)d_in[0];
    const float* qkv_w   = (const float*)d_in[1];
    const float* proj_w  = (const float*)d_in[2];
    const float* proj_b  = (const float*)d_in[3];
    const float* head_w  = (const float*)d_in[4];
    const float* head_b  = (const float*)d_in[5];
    const float* body_w  = (const float*)d_in[6];
    const float* body_b  = (const float*)d_in[7];
    const float* btail_w = (const float*)d_in[8];
    const float* btail_b = (const float*)d_in[9];
    const float* up_w    = (const float*)d_in[10];
    const float* up_b    = (const float*)d_in[11];
    const float* tail_w  = (const float*)d_in[12];
    const float* tail_b  = (const float*)d_in[13];
    const float* c1_w    = (const float*)d_in[14];
    const float* bn1_g   = (const float*)d_in[15];
    const float* bn1_b   = (const float*)d_in[16];
    const float* bn1_m   = (const float*)d_in[17];
    const float* bn1_v   = (const float*)d_in[18];
    const float* c2_w    = (const float*)d_in[19];
    const float* bn2_g   = (const float*)d_in[20];
    const float* bn2_b   = (const float*)d_in[21];
    const float* bn2_m   = (const float*)d_in[22];
    const float* bn2_v   = (const float*)d_in[23];
    const float* c3_w    = (const float*)d_in[24];
    const float* c3_b    = (const float*)d_in[25];
    float* out = (float*)d_out;

    float *p_x, *p_t, *p_qkv, *p_attn, *p_res, *p_bn, *p_m;
    uint32_t *p_xs, *p_h, *p_r, *p_tmp, *p_u, *p_y1, *p_y2, *p_v;
    __nv_bfloat16 *p_uhi, *p_ulo, *p_aqh, *p_aql, *p_aph, *p_apl;
    cudaGetSymbolAddress((void**)&p_x, g_x);
    cudaGetSymbolAddress((void**)&p_t, g_t);
    cudaGetSymbolAddress((void**)&p_qkv, g_qkv);
    cudaGetSymbolAddress((void**)&p_attn, g_attn);
    cudaGetSymbolAddress((void**)&p_res, g_res);
    cudaGetSymbolAddress((void**)&p_xs, g_xs);
    cudaGetSymbolAddress((void**)&p_h, g_h);
    cudaGetSymbolAddress((void**)&p_r, g_r);
    cudaGetSymbolAddress((void**)&p_tmp, g_tmp);
    cudaGetSymbolAddress((void**)&p_u, g_u);
    cudaGetSymbolAddress((void**)&p_y1, g_y1);
    cudaGetSymbolAddress((void**)&p_y2, g_y2);
    cudaGetSymbolAddress((void**)&p_bn, g_bn);
    cudaGetSymbolAddress((void**)&p_v, g_v);
    cudaGetSymbolAddress((void**)&p_m, g_m);
    cudaGetSymbolAddress((void**)&p_uhi, g_uhi);
    cudaGetSymbolAddress((void**)&p_ulo, g_ulo);
    cudaGetSymbolAddress((void**)&p_aqh, g_aqh);
    cudaGetSymbolAddress((void**)&p_aql, g_aql);
    cudaGetSymbolAddress((void**)&p_aph, g_aph);
    cudaGetSymbolAddress((void**)&p_apl, g_apl);

    cudaFuncSetAttribute(k_wgemm, cudaFuncAttributeMaxDynamicSharedMemorySize, SMEM_DYN);
    cudaFuncSetAttribute(k_agemm<0, 0>, cudaFuncAttributeMaxDynamicSharedMemorySize, SMEM_DYN);
    cudaFuncSetAttribute(k_agemm<0, 1>, cudaFuncAttributeMaxDynamicSharedMemorySize, SMEM_DYN);
    cudaFuncSetAttribute(k_agemm<1, 0>, cudaFuncAttributeMaxDynamicSharedMemorySize, SMEM_DYN);
    cudaFuncSetAttribute(k_agemm<2, 1>, cudaFuncAttributeMaxDynamicSharedMemorySize, SMEM_DYN);

    cudaMemcpyAsync(p_x, x, (size_t)512 * 1024 * sizeof(float),
                    cudaMemcpyDeviceToDevice, 0);

    // ---- weight prep: launch order places a full wgemm at kernel idx 5
    //      so ncu (-s 5 -c 1) captures the dominant GEMM. ----
    auto wprep1 = [&](const float* w, size_t uoff, int Cout) {
        k_wwino<<<(Cout * 512 + 255) / 256, 256>>>(w, p_uhi + uoff, p_ulo + uoff, Cout, 512);
    };
    wprep1(head_w, U_HEAD, 512);                               // 0
    k_wtq<<<(8 * 1536 * 512 + 255) / 256, 256>>>(qkv_w, p_aqh, p_aql);  // 1
    k_wtp<<<(8 * 512 * 512 + 255) / 256, 256>>>(proj_w, p_aph, p_apl);  // 2
    wprep1(body_w + (size_t)0 * 512 * 512 * 9, U_BODY(0), 512);         // 3
    wprep1(body_w + (size_t)1 * 512 * 512 * 9, U_BODY(1), 512);         // 4
    // 5: DIAGNOSTIC dummy wgemm (reads stale g_v; g_m overwritten before use)
    k_wgemm<<<dim3(10, 4, 16), 256, SMEM_DYN>>>(p_uhi + U_HEAD, p_ulo + U_HEAD, p_v, p_m,
                                                (long)512 * 512, (long)512 * 640,
                                                (long)512 * 640, 640);
    for (int i = 2; i < 16; i++)
        wprep1(body_w + (size_t)i * 512 * 512 * 9, U_BODY(i), 512);
    wprep1(btail_w, U_BTAIL, 512);
    wprep1(tail_w, U_TAIL, 512);
    wprep1(c1_w, U_C1, 512);
    wprep1(c2_w, U_C2, 512);
    k_wwino<<<(2048 * 512 + 255) / 256, 256>>>(up_w, p_uhi + U_UP, p_ulo + U_UP, 2048, 512);

    const float scale = 0.044194173824159216f;  // 512^-0.5

    // ---- 8 self-attention blocks ----
    for (int i = 0; i < 8; i++) {
        k_agemm<0, 0><<<dim3(16, 8, 1), 256, SMEM_DYN>>>(
            p_aqh + (size_t)i * 1536 * 512, p_aql + (size_t)i * 1536 * 512,
            nullptr, p_x, p_qkv, nullptr, nullptr,
            0, 0, 0, 512, 512, 1024, 1024, 1024, 1.f);
        k_agemm<0, 1><<<dim3(16, 4, 1), 256, SMEM_DYN>>>(
            p_aqh + (size_t)i * 1536 * 512 + (size_t)1024 * 512,
            p_aql + (size_t)i * 1536 * 512 + (size_t)1024 * 512,
            nullptr, p_x, p_t, nullptr, nullptr,
            0, 0, 0, 512, 512, 1024, 512, 1024, 1.f);
        k_agemm<1, 0><<<dim3(16, 8, 8), 256, SMEM_DYN>>>(
            nullptr, nullptr, p_qkv, p_qkv + (size_t)512 * 1024, p_attn,
            nullptr, nullptr,
            64 * 1024, 64 * 1024, 1l << 20, 64, 1024, 1024, 1024, 1024, scale);
        k_softmax<<<8192, 256>>>();
        k_agemm<2, 1><<<dim3(1, 8, 8), 256, SMEM_DYN>>>(
            nullptr, nullptr, p_attn, p_t, p_res, nullptr, nullptr,
            1l << 20, 64, 64 * 1024, 1024, 1024, 512, 1024, 64, 1.f);
        k_agemm<0, 0><<<dim3(16, 4, 1), 256, SMEM_DYN>>>(
            p_aph + (size_t)i * 512 * 512, p_apl + (size_t)i * 512 * 512,
            nullptr, p_res, p_x, proj_b + (size_t)i * 512, p_x,
            0, 0, 0, 512, 512, 1024, 1024, 1024, 1.f);
    }

    // ---- grid transform + BN fold ----
    k_gridsample<<<(512 * 2500 + 255) / 256, 256>>>();
    k_bnprep<<<2, 256>>>(bn1_g, bn1_b, bn1_m, bn1_v, bn2_g, bn2_b, bn2_m, bn2_v);

    // ---- Winograd conv layer helper ----
    auto wlayer = [&](const uint32_t* in, size_t uoff, const float* bias,
                      const float* bnsc, const float* bnsh, const uint32_t* resid,
                      uint32_t* o, int T, int Cout, int relu, int ps) {
        int H = 2 * T;
        int NTpad = (T * T + 63) / 64 * 64;
        k_wino_in<<<(512 * NTpad + 255) / 256, 256>>>(in, p_v, H, T, NTpad);
        k_wgemm<<<dim3(NTpad / 64, Cout / 128, 16), 256, SMEM_DYN>>>(
            p_uhi + uoff, p_ulo + uoff, p_v, p_m,
            (long)Cout * 512, (long)512 * NTpad, (long)Cout * NTpad, NTpad);
        k_wino_out<<<(Cout * T * T + 255) / 256, 256>>>(
            p_m, o, bias, bnsc, bnsh, resid, Cout, T, NTpad, relu, ps);
    };

    // ---- EDSR upsampler (Winograd) ----
    wlayer(p_xs, U_HEAD, head_b, nullptr, nullptr, nullptr, p_h, 25, 512, 0, 0);
    cudaMemcpyAsync(p_r, p_h, (size_t)512 * 2500 * sizeof(uint32_t),
                    cudaMemcpyDeviceToDevice, 0);
    for (int i = 0; i < 8; i++) {
        wlayer(p_r, U_BODY(2 * i), body_b + (size_t)(2 * i) * 512,
               nullptr, nullptr, nullptr, p_tmp, 25, 512, 1, 0);
        wlayer(p_tmp, U_BODY(2 * i + 1), body_b + (size_t)(2 * i + 1) * 512,
               nullptr, nullptr, p_r, p_r, 25, 512, 0, 0);
    }
    wlayer(p_r, U_BTAIL, btail_b, nullptr, nullptr, p_h, p_tmp, 25, 512, 0, 0);
    // up conv 512->2048 + fused pixel shuffle
    wlayer(p_tmp, U_UP, up_b, nullptr, nullptr, nullptr, p_u, 25, 2048, 0, 1);
    wlayer(p_u, U_TAIL, tail_b, nullptr, nullptr, nullptr, p_y1, 50, 512, 0, 0);

    // ---- classifier ----
    wlayer(p_y1, U_C1, nullptr, p_bn, p_bn + 512, nullptr, p_y2, 50, 512, 1, 0);
    wlayer(p_y2, U_C2, nullptr, p_bn + 1024, p_bn + 1536, nullptr, p_y1, 50, 512, 1, 0);
    k_c3<<<(60000 + 255) / 256, 256>>>(c3_w, c3_b, out);
}